// round 2
// baseline (speedup 1.0000x reference)
#include <cuda_runtime.h>
#include <math.h>

#define BB   64
#define TT   1024
#define NDIM 1024
#define MTOT (BB*TT)

// Scratch (allocation-free rule: __device__ globals)
__device__ float g_dec_fea[BB*NDIM];
__device__ float g_scores[MTOT];

// ---------------------------------------------------------------------------
// K0: dec_fea[b,m] = sum_n s_t_hat[b,n] * dec_W[m,n] + dec_b[m]
// grid: 128 blocks x 256 threads; one warp per m, loop over b.
// dec_W row held in registers (read once); s_t_hat (256 KB) stays L2-hot.
// ---------------------------------------------------------------------------
__global__ void dec_fea_kernel(const float* __restrict__ s_t_hat,
                               const float* __restrict__ dec_W,
                               const float* __restrict__ dec_b) {
    const int warp = threadIdx.x >> 5;
    const int lane = threadIdx.x & 31;
    const int m = blockIdx.x * 8 + warp;

    const float* wr = dec_W + (size_t)m * NDIM + lane;
    float w[32];
#pragma unroll
    for (int j = 0; j < 32; ++j) w[j] = wr[j * 32];
    const float bias = dec_b[m];

    for (int b = 0; b < BB; ++b) {
        const float* s = s_t_hat + (size_t)b * NDIM + lane;
        float acc = 0.f;
#pragma unroll
        for (int j = 0; j < 32; ++j) acc += w[j] * s[j * 32];
#pragma unroll
        for (int off = 16; off; off >>= 1)
            acc += __shfl_down_sync(0xffffffffu, acc, off);
        if (lane == 0) g_dec_fea[b * NDIM + m] = acc + bias;
    }
}

// ---------------------------------------------------------------------------
// K1: fused GEMM + tanh·v epilogue.
// scores[row] = sum_m v[m] * tanh( h[row]·W_h[m] + dec_fea[b,m] + cov[row]*W_c[m] )
// Block: 128 rows, loops over all 8 column chunks of 128 (no atomics, fully
// deterministic). 256 threads, 8x8 microtile, TK=16 smem staging (transposed).
// ---------------------------------------------------------------------------
__global__ __launch_bounds__(256, 2)
void score_kernel(const float* __restrict__ h, const float* __restrict__ W_h,
                  const float* __restrict__ W_c, const float* __restrict__ v,
                  const float* __restrict__ coverage) {
    __shared__ float As[16][128];
    __shared__ float Bs[16][128];
    __shared__ float red[128][17];
    __shared__ float score_acc[128];
    __shared__ float dec_s[128], wc_s[128], v_s[128];

    const int tid  = threadIdx.x;
    const int tx   = tid & 15;   // column group (8 cols each)
    const int ty   = tid >> 4;   // row group (8 rows each)
    const int row0 = blockIdx.x * 128;
    const int b    = row0 / TT;  // tiles never straddle a batch boundary

    if (tid < 128) score_acc[tid] = 0.f;

    float cov[8];
#pragma unroll
    for (int i = 0; i < 8; ++i) cov[i] = coverage[row0 + ty * 8 + i];

    for (int nc = 0; nc < NDIM / 128; ++nc) {
        const int m0 = nc * 128;
        if (tid < 128) {
            dec_s[tid] = g_dec_fea[b * NDIM + m0 + tid];
            wc_s[tid]  = W_c[m0 + tid];
            v_s[tid]   = v[m0 + tid];
        }

        float acc[8][8];
#pragma unroll
        for (int i = 0; i < 8; ++i)
#pragma unroll
            for (int j = 0; j < 8; ++j) acc[i][j] = 0.f;

        for (int k0 = 0; k0 < NDIM; k0 += 16) {
            // 128x16 tiles of A (h rows) and B (W_h rows), both K-contiguous.
            int f = tid;
#pragma unroll
            for (int it = 0; it < 2; ++it, f += 256) {
                const int r  = f >> 2;
                const int kq = (f & 3) << 2;
                float4 va = *(const float4*)(h   + (size_t)(row0 + r) * NDIM + k0 + kq);
                As[kq + 0][r] = va.x; As[kq + 1][r] = va.y;
                As[kq + 2][r] = va.z; As[kq + 3][r] = va.w;
                float4 vb = *(const float4*)(W_h + (size_t)(m0  + r) * NDIM + k0 + kq);
                Bs[kq + 0][r] = vb.x; Bs[kq + 1][r] = vb.y;
                Bs[kq + 2][r] = vb.z; Bs[kq + 3][r] = vb.w;
            }
            __syncthreads();
#pragma unroll
            for (int kk = 0; kk < 16; ++kk) {
                float a[8], bb[8];
#pragma unroll
                for (int i = 0; i < 8; ++i) a[i]  = As[kk][ty * 8 + i];
#pragma unroll
                for (int j = 0; j < 8; ++j) bb[j] = Bs[kk][tx * 8 + j];
#pragma unroll
                for (int i = 0; i < 8; ++i)
#pragma unroll
                    for (int j = 0; j < 8; ++j) acc[i][j] += a[i] * bb[j];
            }
            __syncthreads();
        }

        // Fused epilogue: tanh + dot with v, reduce 128 cols per row.
#pragma unroll
        for (int i = 0; i < 8; ++i) {
            float part = 0.f;
#pragma unroll
            for (int j = 0; j < 8; ++j) {
                const int c = tx * 8 + j;
                const float val = acc[i][j] + dec_s[c] + cov[i] * wc_s[c];
                part += tanhf(val) * v_s[c];
            }
            red[ty * 8 + i][tx] = part;
        }
        __syncthreads();
        if (tid < 128) {
            float s = 0.f;
#pragma unroll
            for (int x = 0; x < 16; ++x) s += red[tid][x];
            score_acc[tid] += s;
        }
        __syncthreads();
    }

    if (tid < 128) g_scores[row0 + tid] = score_acc[tid];
}

// ---------------------------------------------------------------------------
// K2: masked softmax + renorm + coverage update. One block per batch row.
// attn[t] = exp(s[t]-max)*mask[t] / sum_t exp(s-max)*mask   (denoms cancel)
// ---------------------------------------------------------------------------
__global__ void softmax_kernel(const float* __restrict__ mask,
                               const float* __restrict__ coverage,
                               float* __restrict__ attn_out,
                               float* __restrict__ cov_out) {
    const int b   = blockIdx.x;
    const int tid = threadIdx.x;          // 256 threads, 4 elems each
    __shared__ float warp_red[8];
    __shared__ float stat[2];

    const float* sc = g_scores + b * TT;
    float sv[4];
    float lmax = -1e30f;
#pragma unroll
    for (int q = 0; q < 4; ++q) {
        sv[q] = sc[tid + 256 * q];
        lmax = fmaxf(lmax, sv[q]);
    }
#pragma unroll
    for (int off = 16; off; off >>= 1)
        lmax = fmaxf(lmax, __shfl_xor_sync(0xffffffffu, lmax, off));
    if ((tid & 31) == 0) warp_red[tid >> 5] = lmax;
    __syncthreads();
    if (tid == 0) {
        float m = warp_red[0];
#pragma unroll
        for (int i = 1; i < 8; ++i) m = fmaxf(m, warp_red[i]);
        stat[0] = m;
    }
    __syncthreads();
    const float M = stat[0];

    float e[4];
    float lsum = 0.f;
#pragma unroll
    for (int q = 0; q < 4; ++q) {
        e[q] = expf(sv[q] - M) * mask[b * TT + tid + 256 * q];
        lsum += e[q];
    }
#pragma unroll
    for (int off = 16; off; off >>= 1)
        lsum += __shfl_xor_sync(0xffffffffu, lsum, off);
    if ((tid & 31) == 0) warp_red[tid >> 5] = lsum;
    __syncthreads();
    if (tid == 0) {
        float s = 0.f;
#pragma unroll
        for (int i = 0; i < 8; ++i) s += warp_red[i];
        stat[1] = 1.0f / s;
    }
    __syncthreads();
    const float inv = stat[1];

#pragma unroll
    for (int q = 0; q < 4; ++q) {
        const int t = tid + 256 * q;
        const float a = e[q] * inv;
        attn_out[b * TT + t] = a;
        cov_out[b * TT + t]  = coverage[b * TT + t] + a;
    }
}

// ---------------------------------------------------------------------------
// K3: c_t[b,n] = sum_t attn[b,t] * h[b,t,n]. Memory-bound (one pass over h).
// grid (64, 8) x 128 threads; attn row staged in smem, coalesced h reads.
// ---------------------------------------------------------------------------
__global__ void ct_kernel(const float* __restrict__ h,
                          const float* __restrict__ attn,
                          float* __restrict__ c_t) {
    const int b = blockIdx.x;
    const int n = blockIdx.y * 128 + threadIdx.x;
    __shared__ float a_s[TT];
    for (int i = threadIdx.x; i < TT; i += 128) a_s[i] = attn[b * TT + i];
    __syncthreads();

    const float* hb = h + (size_t)b * TT * NDIM + n;
    float acc0 = 0.f, acc1 = 0.f, acc2 = 0.f, acc3 = 0.f;
#pragma unroll 4
    for (int t = 0; t < TT; t += 4) {
        acc0 += a_s[t + 0] * hb[(size_t)(t + 0) * NDIM];
        acc1 += a_s[t + 1] * hb[(size_t)(t + 1) * NDIM];
        acc2 += a_s[t + 2] * hb[(size_t)(t + 2) * NDIM];
        acc3 += a_s[t + 3] * hb[(size_t)(t + 3) * NDIM];
    }
    c_t[b * NDIM + n] = (acc0 + acc1) + (acc2 + acc3);
}

// ---------------------------------------------------------------------------
extern "C" void kernel_launch(void* const* d_in, const int* in_sizes, int n_in,
                              void* d_out, int out_size) {
    const float* s_t_hat  = (const float*)d_in[0];
    const float* h        = (const float*)d_in[1];
    const float* mask     = (const float*)d_in[2];
    const float* coverage = (const float*)d_in[3];
    const float* W_h      = (const float*)d_in[4];
    const float* W_c      = (const float*)d_in[5];
    const float* dec_W    = (const float*)d_in[6];
    const float* dec_b    = (const float*)d_in[7];
    const float* v        = (const float*)d_in[8];

    float* out  = (float*)d_out;
    float* c_t  = out;                       // [B, N]
    float* attn = out + (size_t)BB * NDIM;   // [B, T]
    float* covn = attn + (size_t)BB * TT;    // [B, T]

    dec_fea_kernel<<<NDIM / 8, 256>>>(s_t_hat, dec_W, dec_b);
    score_kernel<<<MTOT / 128, 256>>>(h, W_h, W_c, v, coverage);
    softmax_kernel<<<BB, 256>>>(mask, coverage, attn, covn);
    ct_kernel<<<dim3(BB, NDIM / 128), 128>>>(h, attn, c_t);
}

// round 4
// speedup vs baseline: 2.2688x; 2.2688x over previous
#include <cuda_runtime.h>
#include <cuda_bf16.h>
#include <math.h>
#include <stdint.h>

#define BB 64
#define TT 1024
#define NDIM 1024
#define MTOT (BB*TT)

__device__ __align__(16) __nv_bfloat16 g_h_hi[(size_t)MTOT*NDIM];
__device__ __align__(16) __nv_bfloat16 g_h_lo[(size_t)MTOT*NDIM];
__device__ __align__(16) __nv_bfloat16 g_w_hi[(size_t)NDIM*NDIM];
__device__ __align__(16) __nv_bfloat16 g_w_lo[(size_t)NDIM*NDIM];
__device__ float g_dec_fea[BB*NDIM];
__device__ float g_scores[MTOT];

// ---------------- helpers ----------------
__device__ __forceinline__ uint32_t smem_to_u32(const void* p) {
    uint32_t a;
    asm("{ .reg .u64 t; cvta.to.shared.u64 t, %1; cvt.u32.u64 %0, t; }" : "=r"(a) : "l"(p));
    return a;
}
__device__ __forceinline__ void cp16(uint32_t dst, const void* src) {
    asm volatile("cp.async.cg.shared.global [%0], [%1], 16;" :: "r"(dst), "l"(src));
}
#define CP_COMMIT() asm volatile("cp.async.commit_group;" ::: "memory")
#define CP_WAIT_1() asm volatile("cp.async.wait_group 1;" ::: "memory")
#define CP_WAIT_0() asm volatile("cp.async.wait_group 0;" ::: "memory")

__device__ __forceinline__ void ldm_x4(uint32_t* r, uint32_t addr) {
    asm volatile("ldmatrix.sync.aligned.m8n8.x4.shared.b16 {%0,%1,%2,%3}, [%4];"
        : "=r"(r[0]), "=r"(r[1]), "=r"(r[2]), "=r"(r[3]) : "r"(addr));
}
__device__ __forceinline__ void mma16816(float* d, const uint32_t* a, const uint32_t* b) {
    asm volatile("mma.sync.aligned.m16n8k16.row.col.f32.bf16.bf16.f32 "
        "{%0,%1,%2,%3}, {%4,%5,%6,%7}, {%8,%9}, {%0,%1,%2,%3};"
        : "+f"(d[0]), "+f"(d[1]), "+f"(d[2]), "+f"(d[3])
        : "r"(a[0]), "r"(a[1]), "r"(a[2]), "r"(a[3]), "r"(b[0]), "r"(b[1]));
}

// ---------------- split f32 -> bf16 hi/lo ----------------
__global__ void split_kernel(const float* __restrict__ src, int is_w) {
    __nv_bfloat162* hi = (__nv_bfloat162*)(is_w ? g_w_hi : g_h_hi);
    __nv_bfloat162* lo = (__nv_bfloat162*)(is_w ? g_w_lo : g_h_lo);
    const size_t i = (size_t)blockIdx.x * 256 + threadIdx.x;
    float4 x = ((const float4*)src)[i];
    __nv_bfloat162 h01 = __floats2bfloat162_rn(x.x, x.y);
    __nv_bfloat162 h23 = __floats2bfloat162_rn(x.z, x.w);
    __nv_bfloat162 l01 = __floats2bfloat162_rn(x.x - __bfloat162float(h01.x),
                                               x.y - __bfloat162float(h01.y));
    __nv_bfloat162 l23 = __floats2bfloat162_rn(x.z - __bfloat162float(h23.x),
                                               x.w - __bfloat162float(h23.y));
    hi[2*i] = h01; hi[2*i+1] = h23;
    lo[2*i] = l01; lo[2*i+1] = l23;
}

// ---------------- dec_fea ----------------
__global__ void dec_fea_kernel(const float* __restrict__ s_t_hat,
                               const float* __restrict__ dec_W,
                               const float* __restrict__ dec_b) {
    const int warp = threadIdx.x >> 5, lane = threadIdx.x & 31;
    const int m = blockIdx.x * 8 + warp;
    const float* wr = dec_W + (size_t)m * NDIM + lane;
    float w[32];
#pragma unroll
    for (int j = 0; j < 32; ++j) w[j] = wr[j * 32];
    const float bias = dec_b[m];
    for (int b = 0; b < BB; ++b) {
        const float* s = s_t_hat + (size_t)b * NDIM + lane;
        float acc = 0.f;
#pragma unroll
        for (int j = 0; j < 32; ++j) acc += w[j] * s[j * 32];
#pragma unroll
        for (int off = 16; off; off >>= 1) acc += __shfl_down_sync(0xffffffffu, acc, off);
        if (lane == 0) g_dec_fea[b * NDIM + m] = acc + bias;
    }
}

// ---------------- score kernel: bf16 hi/lo 3-pass mma.sync ----------------
// CTA: 128 rows x 128-col chunk (x8 chunks), Kc=32, 3-stage cp.async pipeline.
// Warp grid 2x4; warp tile 64x32 -> 4x4 m16n8k16 fragments, fp32 accum.
#define PITCH   80
#define BUFB    10240           /* 128 rows * 80B */
#define STGB    40960           /* Ahi,Alo,Bhi,Blo */
#define OFF_DEC (3*STGB)
#define OFF_WC  (OFF_DEC+512)
#define OFF_V   (OFF_WC+512)
#define OFF_COV (OFF_V+512)
#define OFF_RED (OFF_COV+512)   /* 128*4 floats */
#define OFF_SC  (OFF_RED+2048)
#define SMEM_SZ (OFF_SC+512)    /* 127488 B */

__device__ __forceinline__ void load_stage(uint32_t sb, char* smem, int s,
                                           int row0, int m0, int k0, int tid) {
    const uint32_t base = sb + s * STGB;
#pragma unroll
    for (int it = 0; it < 2; ++it) {
        const int idx = tid + it * 256;
        const int row = idx >> 2, ch = idx & 3;
        const uint32_t o = row * PITCH + ch * 16;
        const size_t gA = (size_t)(row0 + row) * NDIM + k0 + ch * 8;
        const size_t gB = (size_t)(m0  + row) * NDIM + k0 + ch * 8;
        cp16(base + o,            g_h_hi + gA);
        cp16(base + BUFB + o,     g_h_lo + gA);
        cp16(base + 2*BUFB + o,   g_w_hi + gB);
        cp16(base + 3*BUFB + o,   g_w_lo + gB);
    }
}

__global__ __launch_bounds__(256, 1)
void score_mma_kernel(const float* __restrict__ coverage,
                      const float* __restrict__ W_c,
                      const float* __restrict__ v) {
    extern __shared__ char smem[];
    const uint32_t sb = smem_to_u32(smem);
    const int tid  = threadIdx.x;
    const int lane = tid & 31;
    const int wid  = tid >> 5;
    const int wm   = wid >> 2;          // 0..1  (64-row slab)
    const int wn   = wid & 3;           // 0..3  (32-col slab)
    const int row0 = blockIdx.x * 128;
    const int b    = row0 / TT;

    float* dec_s = (float*)(smem + OFF_DEC);
    float* wc_s  = (float*)(smem + OFF_WC);
    float* v_s   = (float*)(smem + OFF_V);
    float* cov_s = (float*)(smem + OFF_COV);
    float* red   = (float*)(smem + OFF_RED);   // [128][4]
    float* sc_s  = (float*)(smem + OFF_SC);

    if (tid < 128) {
        cov_s[tid] = coverage[row0 + tid];
        sc_s[tid]  = 0.f;
    }

    // precomputed fragment addresses (stage-relative)
    // A (ldmatrix.x4): row = wm*64 + mi*16 + (l&7) + ((l>>3)&1)*8 ; +((l>>4)*16) bytes
    const uint32_t aoff = (uint32_t)((wm*64 + (lane&7) + ((lane>>3)&1)*8) * PITCH + (lane>>4)*16);
    // B (2x LDS.32): row = wn*32 + ni*8 + (l>>2) ; byte = (l&3)*4
    const uint32_t boff = (uint32_t)((wn*32 + (lane>>2)) * PITCH + (lane&3)*4);

    for (int nc = 0; nc < 8; ++nc) {
        const int m0 = nc * 128;
        if (tid < 128) {
            dec_s[tid] = g_dec_fea[b * NDIM + m0 + tid];
            wc_s[tid]  = W_c[m0 + tid];
            v_s[tid]   = v[m0 + tid];
        }

        float acc[4][4][4];
#pragma unroll
        for (int mi = 0; mi < 4; ++mi)
#pragma unroll
            for (int ni = 0; ni < 4; ++ni)
#pragma unroll
                for (int q = 0; q < 4; ++q) acc[mi][ni][q] = 0.f;

        load_stage(sb, smem, 0, row0, m0, 0, tid);  CP_COMMIT();
        load_stage(sb, smem, 1, row0, m0, 32, tid); CP_COMMIT();

        for (int ks = 0; ks < 32; ++ks) {
            const int s = ks % 3;
            if (ks + 2 < 32) CP_WAIT_1(); else CP_WAIT_0();
            __syncthreads();
            if (ks + 2 < 32) {
                load_stage(sb, smem, (ks + 2) % 3, row0, m0, (ks + 2) * 32, tid);
                CP_COMMIT();
            }
            const uint32_t stg = sb + s * STGB;
#pragma unroll
            for (int kk = 0; kk < 2; ++kk) {
                uint32_t ah[4][4], al[4][4];
#pragma unroll
                for (int mi = 0; mi < 4; ++mi) {
                    const uint32_t a = stg + aoff + mi * (16 * PITCH) + kk * 32;
                    ldm_x4(ah[mi], a);
                    ldm_x4(al[mi], a + BUFB);
                }
                uint32_t bh[4][2], bl[4][2];
#pragma unroll
                for (int ni = 0; ni < 4; ++ni) {
                    const uint32_t bAddr = stg + 2*BUFB + boff + ni * (8 * PITCH) + kk * 32;
                    bh[ni][0] = *(const uint32_t*)(smem + (bAddr - sb));
                    bh[ni][1] = *(const uint32_t*)(smem + (bAddr - sb) + 16);
                    bl[ni][0] = *(const uint32_t*)(smem + (bAddr - sb) + BUFB);
                    bl[ni][1] = *(const uint32_t*)(smem + (bAddr - sb) + BUFB + 16);
                }
#pragma unroll
                for (int mi = 0; mi < 4; ++mi)
#pragma unroll
                    for (int ni = 0; ni < 4; ++ni) {
                        mma16816(acc[mi][ni], ah[mi], bh[ni]);
                        mma16816(acc[mi][ni], al[mi], bh[ni]);
                        mma16816(acc[mi][ni], ah[mi], bl[ni]);
                    }
            }
        }

        // fused epilogue: tanh + dot with v over this 128-col chunk
        float part[4][2];
#pragma unroll
        for (int mi = 0; mi < 4; ++mi) { part[mi][0] = 0.f; part[mi][1] = 0.f; }
#pragma unroll
        for (int mi = 0; mi < 4; ++mi) {
            const int r0 = wm*64 + mi*16 + (lane >> 2);
            const float cv0 = cov_s[r0], cv1 = cov_s[r0 + 8];
#pragma unroll
            for (int ni = 0; ni < 4; ++ni) {
                const int c0 = wn*32 + ni*8 + (lane & 3)*2;
                const float d0 = dec_s[c0],  d1 = dec_s[c0+1];
                const float w0 = wc_s[c0],   w1 = wc_s[c0+1];
                const float q0 = v_s[c0],    q1 = v_s[c0+1];
                part[mi][0] += tanhf(acc[mi][ni][0] + d0 + cv0*w0) * q0
                             + tanhf(acc[mi][ni][1] + d1 + cv0*w1) * q1;
                part[mi][1] += tanhf(acc[mi][ni][2] + d0 + cv1*w0) * q0
                             + tanhf(acc[mi][ni][3] + d1 + cv1*w1) * q1;
            }
        }
#pragma unroll
        for (int mi = 0; mi < 4; ++mi)
#pragma unroll
            for (int i = 0; i < 2; ++i) {
                float p = part[mi][i];
                p += __shfl_xor_sync(0xffffffffu, p, 1);
                p += __shfl_xor_sync(0xffffffffu, p, 2);
                if ((lane & 3) == 0)
                    red[(wm*64 + mi*16 + (lane >> 2) + 8*i) * 4 + wn] = p;
            }
        __syncthreads();
        if (tid < 128)
            sc_s[tid] += red[tid*4] + red[tid*4+1] + red[tid*4+2] + red[tid*4+3];
        __syncthreads();
    }

    if (tid < 128) g_scores[row0 + tid] = sc_s[tid];
}

// ---------------- softmax ----------------
__global__ void softmax_kernel(const float* __restrict__ mask,
                               const float* __restrict__ coverage,
                               float* __restrict__ attn_out,
                               float* __restrict__ cov_out) {
    const int b = blockIdx.x, tid = threadIdx.x;
    __shared__ float wr_[8], stat[2];
    const float* sc = g_scores + b * TT;
    float sv[4], lmax = -1e30f;
#pragma unroll
    for (int q = 0; q < 4; ++q) { sv[q] = sc[tid + 256 * q]; lmax = fmaxf(lmax, sv[q]); }
#pragma unroll
    for (int off = 16; off; off >>= 1) lmax = fmaxf(lmax, __shfl_xor_sync(0xffffffffu, lmax, off));
    if ((tid & 31) == 0) wr_[tid >> 5] = lmax;
    __syncthreads();
    if (tid == 0) {
        float m = wr_[0];
#pragma unroll
        for (int i = 1; i < 8; ++i) m = fmaxf(m, wr_[i]);
        stat[0] = m;
    }
    __syncthreads();
    const float M = stat[0];
    float e[4], lsum = 0.f;
#pragma unroll
    for (int q = 0; q < 4; ++q) { e[q] = expf(sv[q] - M) * mask[b * TT + tid + 256 * q]; lsum += e[q]; }
#pragma unroll
    for (int off = 16; off; off >>= 1) lsum += __shfl_xor_sync(0xffffffffu, lsum, off);
    if ((tid & 31) == 0) wr_[tid >> 5] = lsum;
    __syncthreads();
    if (tid == 0) {
        float s = 0.f;
#pragma unroll
        for (int i = 0; i < 8; ++i) s += wr_[i];
        stat[1] = 1.0f / s;
    }
    __syncthreads();
    const float inv = stat[1];
#pragma unroll
    for (int q = 0; q < 4; ++q) {
        const int t = tid + 256 * q;
        const float a = e[q] * inv;
        attn_out[b * TT + t] = a;
        cov_out[b * TT + t]  = coverage[b * TT + t] + a;
    }
}

// ---------------- c_t ----------------
__global__ void ct_kernel(const float* __restrict__ h,
                          const float* __restrict__ attn,
                          float* __restrict__ c_t) {
    const int b = blockIdx.x;
    const int n = blockIdx.y * 128 + threadIdx.x;
    __shared__ float a_s[TT];
    for (int i = threadIdx.x; i < TT; i += 128) a_s[i] = attn[b * TT + i];
    __syncthreads();
    const float* hb = h + (size_t)b * TT * NDIM + n;
    float a0 = 0.f, a1 = 0.f, a2 = 0.f, a3 = 0.f;
#pragma unroll 4
    for (int t = 0; t < TT; t += 4) {
        a0 += a_s[t + 0] * hb[(size_t)(t + 0) * NDIM];
        a1 += a_s[t + 1] * hb[(size_t)(t + 1) * NDIM];
        a2 += a_s[t + 2] * hb[(size_t)(t + 2) * NDIM];
        a3 += a_s[t + 3] * hb[(size_t)(t + 3) * NDIM];
    }
    c_t[b * NDIM + n] = (a0 + a1) + (a2 + a3);
}

// ---------------------------------------------------------------------------
extern "C" void kernel_launch(void* const* d_in, const int* in_sizes, int n_in,
                              void* d_out, int out_size) {
    const float* s_t_hat  = (const float*)d_in[0];
    const float* h        = (const float*)d_in[1];
    const float* mask     = (const float*)d_in[2];
    const float* coverage = (const float*)d_in[3];
    const float* W_h      = (const float*)d_in[4];
    const float* W_c      = (const float*)d_in[5];
    const float* dec_W    = (const float*)d_in[6];
    const float* dec_b    = (const float*)d_in[7];
    const float* v        = (const float*)d_in[8];

    float* out  = (float*)d_out;
    float* c_t  = out;
    float* attn = out + (size_t)BB * NDIM;
    float* covn = attn + (size_t)BB * TT;

    cudaFuncSetAttribute(score_mma_kernel,
                         cudaFuncAttributeMaxDynamicSharedMemorySize, SMEM_SZ);

    split_kernel<<<(int)((size_t)MTOT * NDIM / 4 / 256), 256>>>(h, 0);
    split_kernel<<<NDIM * NDIM / 4 / 256, 256>>>(W_h, 1);
    dec_fea_kernel<<<NDIM / 8, 256>>>(s_t_hat, dec_W, dec_b);
    score_mma_kernel<<<MTOT / 128, 256, SMEM_SZ>>>(coverage, W_c, v);
    softmax_kernel<<<BB, 256>>>(mask, coverage, attn, covn);
    ct_kernel<<<dim3(BB, NDIM / 128), 128>>>(h, attn, c_t);
}

// round 5
// speedup vs baseline: 2.3145x; 1.0202x over previous
#include <cuda_runtime.h>
#include <cuda_bf16.h>
#include <math.h>
#include <stdint.h>

#define BB 64
#define TT 1024
#define NDIM 1024
#define MTOT (BB*TT)

__device__ __align__(16) __nv_bfloat16 g_h_hi[(size_t)MTOT*NDIM];
__device__ __align__(16) __nv_bfloat16 g_h_lo[(size_t)MTOT*NDIM];
__device__ __align__(16) __nv_bfloat16 g_w_hi[(size_t)NDIM*NDIM];
__device__ __align__(16) __nv_bfloat16 g_w_lo[(size_t)NDIM*NDIM];
__device__ float g_dec_fea[BB*NDIM];
__device__ float g_scores[MTOT];

// ---------------- helpers ----------------
__device__ __forceinline__ uint32_t smem_to_u32(const void* p) {
    uint32_t a;
    asm("{ .reg .u64 t; cvta.to.shared.u64 t, %1; cvt.u32.u64 %0, t; }" : "=r"(a) : "l"(p));
    return a;
}
__device__ __forceinline__ void cp16(uint32_t dst, const void* src) {
    asm volatile("cp.async.cg.shared.global [%0], [%1], 16;" :: "r"(dst), "l"(src));
}
#define CP_COMMIT() asm volatile("cp.async.commit_group;" ::: "memory")
#define CP_WAIT_1() asm volatile("cp.async.wait_group 1;" ::: "memory")
#define CP_WAIT_0() asm volatile("cp.async.wait_group 0;" ::: "memory")

__device__ __forceinline__ void ldm_x4(uint32_t* r, uint32_t addr) {
    asm volatile("ldmatrix.sync.aligned.m8n8.x4.shared.b16 {%0,%1,%2,%3}, [%4];"
        : "=r"(r[0]), "=r"(r[1]), "=r"(r[2]), "=r"(r[3]) : "r"(addr));
}
__device__ __forceinline__ void mma16816(float* d, const uint32_t* a, const uint32_t* b) {
    asm volatile("mma.sync.aligned.m16n8k16.row.col.f32.bf16.bf16.f32 "
        "{%0,%1,%2,%3}, {%4,%5,%6,%7}, {%8,%9}, {%0,%1,%2,%3};"
        : "+f"(d[0]), "+f"(d[1]), "+f"(d[2]), "+f"(d[3])
        : "r"(a[0]), "r"(a[1]), "r"(a[2]), "r"(a[3]), "r"(b[0]), "r"(b[1]));
}

// ---------------- split f32 -> bf16 hi/lo ----------------
__global__ void split_kernel(const float* __restrict__ src, int is_w) {
    __nv_bfloat162* hi = (__nv_bfloat162*)(is_w ? g_w_hi : g_h_hi);
    __nv_bfloat162* lo = (__nv_bfloat162*)(is_w ? g_w_lo : g_h_lo);
    const size_t i = (size_t)blockIdx.x * 256 + threadIdx.x;
    float4 x = ((const float4*)src)[i];
    __nv_bfloat162 h01 = __floats2bfloat162_rn(x.x, x.y);
    __nv_bfloat162 h23 = __floats2bfloat162_rn(x.z, x.w);
    __nv_bfloat162 l01 = __floats2bfloat162_rn(x.x - __bfloat162float(h01.x),
                                               x.y - __bfloat162float(h01.y));
    __nv_bfloat162 l23 = __floats2bfloat162_rn(x.z - __bfloat162float(h23.x),
                                               x.w - __bfloat162float(h23.y));
    hi[2*i] = h01; hi[2*i+1] = h23;
    lo[2*i] = l01; lo[2*i+1] = l23;
}

// ---------------- dec_fea ----------------
__global__ void dec_fea_kernel(const float* __restrict__ s_t_hat,
                               const float* __restrict__ dec_W,
                               const float* __restrict__ dec_b) {
    const int warp = threadIdx.x >> 5, lane = threadIdx.x & 31;
    const int m = blockIdx.x * 8 + warp;
    const float* wr = dec_W + (size_t)m * NDIM + lane;
    float w[32];
#pragma unroll
    for (int j = 0; j < 32; ++j) w[j] = wr[j * 32];
    const float bias = dec_b[m];
    for (int b = 0; b < BB; ++b) {
        const float* s = s_t_hat + (size_t)b * NDIM + lane;
        float acc = 0.f;
#pragma unroll
        for (int j = 0; j < 32; ++j) acc += w[j] * s[j * 32];
#pragma unroll
        for (int off = 16; off; off >>= 1) acc += __shfl_down_sync(0xffffffffu, acc, off);
        if (lane == 0) g_dec_fea[b * NDIM + m] = acc + bias;
    }
}

// ---------------- score kernel: bf16 hi/lo 3-pass mma.sync ----------------
// CTA: 128 rows x 128-col chunk (x8), Kc=32, 3-stage cp.async pipeline.
// 512 threads, warp grid 4x4, warp tile 32x32 -> 2x4 m16n8k16 frags.
#define PITCH   80
#define BUFB    10240           /* 128 rows * 80B */
#define STGB    40960           /* Ahi,Alo,Bhi,Blo */
#define OFF_DEC (3*STGB)
#define OFF_WC  (OFF_DEC+512)
#define OFF_V   (OFF_WC+512)
#define OFF_COV (OFF_V+512)
#define OFF_RED (OFF_COV+512)   /* 128*4 floats */
#define OFF_SC  (OFF_RED+2048)
#define SMEM_SZ (OFF_SC+512)    /* 127488 B */

__device__ __forceinline__ void load_stage(uint32_t sb, int s,
                                           int row0, int m0, int k0, int tid) {
    const uint32_t base = sb + s * STGB;
    const int row = tid >> 2, ch = tid & 3;          // 512 threads = 128 rows x 4 chunks
    const uint32_t o = row * PITCH + ch * 16;
    const size_t gA = (size_t)(row0 + row) * NDIM + k0 + ch * 8;
    const size_t gB = (size_t)(m0  + row) * NDIM + k0 + ch * 8;
    cp16(base + o,          g_h_hi + gA);
    cp16(base + BUFB + o,   g_h_lo + gA);
    cp16(base + 2*BUFB + o, g_w_hi + gB);
    cp16(base + 3*BUFB + o, g_w_lo + gB);
}

__global__ __launch_bounds__(512, 1)
void score_mma_kernel(const float* __restrict__ coverage,
                      const float* __restrict__ W_c,
                      const float* __restrict__ v) {
    extern __shared__ char smem[];
    const uint32_t sb = smem_to_u32(smem);
    const int tid  = threadIdx.x;
    const int lane = tid & 31;
    const int wid  = tid >> 5;
    const int wm   = wid >> 2;          // 0..3  (32-row slab)
    const int wn   = wid & 3;           // 0..3  (32-col slab)
    const int row0 = blockIdx.x * 128;
    const int b    = row0 / TT;

    float* dec_s = (float*)(smem + OFF_DEC);
    float* wc_s  = (float*)(smem + OFF_WC);
    float* v_s   = (float*)(smem + OFF_V);
    float* cov_s = (float*)(smem + OFF_COV);
    float* red   = (float*)(smem + OFF_RED);   // [128][4]
    float* sc_s  = (float*)(smem + OFF_SC);

    if (tid < 128) {
        cov_s[tid] = coverage[row0 + tid];
        sc_s[tid]  = 0.f;
    }

    // A (ldmatrix.x4): row = wm*32 + (l&7) + ((l>>3)&1)*8, byte (l>>4)*16
    const uint32_t aoff = (uint32_t)((wm*32 + (lane&7) + ((lane>>3)&1)*8) * PITCH + (lane>>4)*16);
    // B (ldmatrix.x4): row = wn*32 + (l&7), byte (l>>3)*16  (r0..r3 = k0-7,8-15,16-23,24-31)
    const uint32_t boff = (uint32_t)((wn*32 + (lane&7)) * PITCH + (lane>>3)*16);

    for (int nc = 0; nc < 8; ++nc) {
        const int m0 = nc * 128;
        if (tid < 128) {
            dec_s[tid] = g_dec_fea[b * NDIM + m0 + tid];
            wc_s[tid]  = W_c[m0 + tid];
            v_s[tid]   = v[m0 + tid];
        }

        float acc[2][4][4];
#pragma unroll
        for (int mi = 0; mi < 2; ++mi)
#pragma unroll
            for (int ni = 0; ni < 4; ++ni)
#pragma unroll
                for (int q = 0; q < 4; ++q) acc[mi][ni][q] = 0.f;

        load_stage(sb, 0, row0, m0, 0, tid);  CP_COMMIT();
        load_stage(sb, 1, row0, m0, 32, tid); CP_COMMIT();

        for (int ks = 0; ks < 32; ++ks) {
            const int s = ks % 3;
            if (ks + 2 < 32) CP_WAIT_1(); else CP_WAIT_0();
            __syncthreads();
            if (ks + 2 < 32) {
                load_stage(sb, (ks + 2) % 3, row0, m0, (ks + 2) * 32, tid);
                CP_COMMIT();
            }
            const uint32_t stg = sb + s * STGB;

            // B fragments: both kk halves in one x4 per (ni, buf)
            uint32_t bh[4][4], bl[4][4];
#pragma unroll
            for (int ni = 0; ni < 4; ++ni) {
                const uint32_t bAddr = stg + 2*BUFB + boff + ni * (8 * PITCH);
                ldm_x4(bh[ni], bAddr);
                ldm_x4(bl[ni], bAddr + BUFB);
            }
#pragma unroll
            for (int kk = 0; kk < 2; ++kk) {
                uint32_t ah[2][4], al[2][4];
#pragma unroll
                for (int mi = 0; mi < 2; ++mi) {
                    const uint32_t a = stg + aoff + mi * (16 * PITCH) + kk * 32;
                    ldm_x4(ah[mi], a);
                    ldm_x4(al[mi], a + BUFB);
                }
#pragma unroll
                for (int mi = 0; mi < 2; ++mi)
#pragma unroll
                    for (int ni = 0; ni < 4; ++ni) {
                        mma16816(acc[mi][ni], ah[mi], &bh[ni][kk*2]);
                        mma16816(acc[mi][ni], al[mi], &bh[ni][kk*2]);
                        mma16816(acc[mi][ni], ah[mi], &bl[ni][kk*2]);
                    }
            }
        }

        // fused epilogue: tanh + dot with v over this 128-col chunk
        float part[2][2];
#pragma unroll
        for (int mi = 0; mi < 2; ++mi) { part[mi][0] = 0.f; part[mi][1] = 0.f; }
#pragma unroll
        for (int mi = 0; mi < 2; ++mi) {
            const int r0 = wm*32 + mi*16 + (lane >> 2);
            const float cv0 = cov_s[r0], cv1 = cov_s[r0 + 8];
#pragma unroll
            for (int ni = 0; ni < 4; ++ni) {
                const int c0 = wn*32 + ni*8 + (lane & 3)*2;
                const float d0 = dec_s[c0],  d1 = dec_s[c0+1];
                const float w0 = wc_s[c0],   w1 = wc_s[c0+1];
                const float q0 = v_s[c0],    q1 = v_s[c0+1];
                part[mi][0] += tanhf(acc[mi][ni][0] + d0 + cv0*w0) * q0
                             + tanhf(acc[mi][ni][1] + d1 + cv0*w1) * q1;
                part[mi][1] += tanhf(acc[mi][ni][2] + d0 + cv1*w0) * q0
                             + tanhf(acc[mi][ni][3] + d1 + cv1*w1) * q1;
            }
        }
#pragma unroll
        for (int mi = 0; mi < 2; ++mi)
#pragma unroll
            for (int i = 0; i < 2; ++i) {
                float p = part[mi][i];
                p += __shfl_xor_sync(0xffffffffu, p, 1);
                p += __shfl_xor_sync(0xffffffffu, p, 2);
                if ((lane & 3) == 0)
                    red[(wm*32 + mi*16 + (lane >> 2) + 8*i) * 4 + wn] = p;
            }
        __syncthreads();
        if (tid < 128)
            sc_s[tid] += red[tid*4] + red[tid*4+1] + red[tid*4+2] + red[tid*4+3];
        __syncthreads();
    }

    if (tid < 128) g_scores[row0 + tid] = sc_s[tid];
}

// ---------------- softmax ----------------
__global__ void softmax_kernel(const float* __restrict__ mask,
                               const float* __restrict__ coverage,
                               float* __restrict__ attn_out,
                               float* __restrict__ cov_out) {
    const int b = blockIdx.x, tid = threadIdx.x;
    __shared__ float wr_[8], stat[2];
    const float* sc = g_scores + b * TT;
    float sv[4], lmax = -1e30f;
#pragma unroll
    for (int q = 0; q < 4; ++q) { sv[q] = sc[tid + 256 * q]; lmax = fmaxf(lmax, sv[q]); }
#pragma unroll
    for (int off = 16; off; off >>= 1) lmax = fmaxf(lmax, __shfl_xor_sync(0xffffffffu, lmax, off));
    if ((tid & 31) == 0) wr_[tid >> 5] = lmax;
    __syncthreads();
    if (tid == 0) {
        float m = wr_[0];
#pragma unroll
        for (int i = 1; i < 8; ++i) m = fmaxf(m, wr_[i]);
        stat[0] = m;
    }
    __syncthreads();
    const float M = stat[0];
    float e[4], lsum = 0.f;
#pragma unroll
    for (int q = 0; q < 4; ++q) { e[q] = expf(sv[q] - M) * mask[b * TT + tid + 256 * q]; lsum += e[q]; }
#pragma unroll
    for (int off = 16; off; off >>= 1) lsum += __shfl_xor_sync(0xffffffffu, lsum, off);
    if ((tid & 31) == 0) wr_[tid >> 5] = lsum;
    __syncthreads();
    if (tid == 0) {
        float s = 0.f;
#pragma unroll
        for (int i = 0; i < 8; ++i) s += wr_[i];
        stat[1] = 1.0f / s;
    }
    __syncthreads();
    const float inv = stat[1];
#pragma unroll
    for (int q = 0; q < 4; ++q) {
        const int t = tid + 256 * q;
        const float a = e[q] * inv;
        attn_out[b * TT + t] = a;
        cov_out[b * TT + t]  = coverage[b * TT + t] + a;
    }
}

// ---------------- c_t ----------------
__global__ void ct_kernel(const float* __restrict__ h,
                          const float* __restrict__ attn,
                          float* __restrict__ c_t) {
    const int b = blockIdx.x;
    const int n = blockIdx.y * 128 + threadIdx.x;
    __shared__ float a_s[TT];
    for (int i = threadIdx.x; i < TT; i += 128) a_s[i] = attn[b * TT + i];
    __syncthreads();
    const float* hb = h + (size_t)b * TT * NDIM + n;
    float a0 = 0.f, a1 = 0.f, a2 = 0.f, a3 = 0.f;
#pragma unroll 4
    for (int t = 0; t < TT; t += 4) {
        a0 += a_s[t + 0] * hb[(size_t)(t + 0) * NDIM];
        a1 += a_s[t + 1] * hb[(size_t)(t + 1) * NDIM];
        a2 += a_s[t + 2] * hb[(size_t)(t + 2) * NDIM];
        a3 += a_s[t + 3] * hb[(size_t)(t + 3) * NDIM];
    }
    c_t[b * NDIM + n] = (a0 + a1) + (a2 + a3);
}

// ---------------------------------------------------------------------------
extern "C" void kernel_launch(void* const* d_in, const int* in_sizes, int n_in,
                              void* d_out, int out_size) {
    const float* s_t_hat  = (const float*)d_in[0];
    const float* h        = (const float*)d_in[1];
    const float* mask     = (const float*)d_in[2];
    const float* coverage = (const float*)d_in[3];
    const float* W_h      = (const float*)d_in[4];
    const float* W_c      = (const float*)d_in[5];
    const float* dec_W    = (const float*)d_in[6];
    const float* dec_b    = (const float*)d_in[7];
    const float* v        = (const float*)d_in[8];

    float* out  = (float*)d_out;
    float* c_t  = out;
    float* attn = out + (size_t)BB * NDIM;
    float* covn = attn + (size_t)BB * TT;

    cudaFuncSetAttribute(score_mma_kernel,
                         cudaFuncAttributeMaxDynamicSharedMemorySize, SMEM_SZ);

    split_kernel<<<(int)((size_t)MTOT * NDIM / 4 / 256), 256>>>(h, 0);
    split_kernel<<<NDIM * NDIM / 4 / 256, 256>>>(W_h, 1);
    dec_fea_kernel<<<NDIM / 8, 256>>>(s_t_hat, dec_W, dec_b);
    score_mma_kernel<<<MTOT / 128, 512, SMEM_SZ>>>(coverage, W_c, v);
    softmax_kernel<<<BB, 256>>>(mask, coverage, attn, covn);
    ct_kernel<<<dim3(BB, NDIM / 128), 128>>>(h, attn, c_t);
}

// round 6
// speedup vs baseline: 2.4975x; 1.0791x over previous
#include <cuda_runtime.h>
#include <cuda_bf16.h>
#include <math.h>
#include <stdint.h>

#define BB 64
#define TT 1024
#define NDIM 1024
#define MTOT (BB*TT)

__device__ __align__(16) __nv_bfloat16 g_h_hi[(size_t)MTOT*NDIM];
__device__ __align__(16) __nv_bfloat16 g_h_lo[(size_t)MTOT*NDIM];
__device__ __align__(16) __nv_bfloat16 g_w_hi[(size_t)NDIM*NDIM];
__device__ __align__(16) __nv_bfloat16 g_w_lo[(size_t)NDIM*NDIM];
__device__ float g_dec_fea[BB*NDIM];
__device__ float g_scores[MTOT];
__device__ float g_ct_part[4*BB*NDIM];

// ---------------- helpers ----------------
__device__ __forceinline__ uint32_t smem_to_u32(const void* p) {
    uint32_t a;
    asm("{ .reg .u64 t; cvta.to.shared.u64 t, %1; cvt.u32.u64 %0, t; }" : "=r"(a) : "l"(p));
    return a;
}
__device__ __forceinline__ void cp16(uint32_t dst, const void* src) {
    asm volatile("cp.async.cg.shared.global [%0], [%1], 16;" :: "r"(dst), "l"(src));
}
#define CP_COMMIT() asm volatile("cp.async.commit_group;" ::: "memory")
#define CP_WAIT_1() asm volatile("cp.async.wait_group 1;" ::: "memory")
#define CP_WAIT_0() asm volatile("cp.async.wait_group 0;" ::: "memory")

__device__ __forceinline__ void ldm_x4(uint32_t* r, uint32_t addr) {
    asm volatile("ldmatrix.sync.aligned.m8n8.x4.shared.b16 {%0,%1,%2,%3}, [%4];"
        : "=r"(r[0]), "=r"(r[1]), "=r"(r[2]), "=r"(r[3]) : "r"(addr));
}
__device__ __forceinline__ void ldm_x2(uint32_t* r, uint32_t addr) {
    asm volatile("ldmatrix.sync.aligned.m8n8.x2.shared.b16 {%0,%1}, [%2];"
        : "=r"(r[0]), "=r"(r[1]) : "r"(addr));
}
__device__ __forceinline__ void mma16816(float* d, const uint32_t* a, const uint32_t* b) {
    asm volatile("mma.sync.aligned.m16n8k16.row.col.f32.bf16.bf16.f32 "
        "{%0,%1,%2,%3}, {%4,%5,%6,%7}, {%8,%9}, {%0,%1,%2,%3};"
        : "+f"(d[0]), "+f"(d[1]), "+f"(d[2]), "+f"(d[3])
        : "r"(a[0]), "r"(a[1]), "r"(a[2]), "r"(a[3]), "r"(b[0]), "r"(b[1]));
}

// ---------------- split f32 -> bf16 hi/lo ----------------
__global__ void split_kernel(const float* __restrict__ src, int is_w) {
    __nv_bfloat162* hi = (__nv_bfloat162*)(is_w ? g_w_hi : g_h_hi);
    __nv_bfloat162* lo = (__nv_bfloat162*)(is_w ? g_w_lo : g_h_lo);
    const size_t i = (size_t)blockIdx.x * 256 + threadIdx.x;
    float4 x = ((const float4*)src)[i];
    __nv_bfloat162 h01 = __floats2bfloat162_rn(x.x, x.y);
    __nv_bfloat162 h23 = __floats2bfloat162_rn(x.z, x.w);
    __nv_bfloat162 l01 = __floats2bfloat162_rn(x.x - __bfloat162float(h01.x),
                                               x.y - __bfloat162float(h01.y));
    __nv_bfloat162 l23 = __floats2bfloat162_rn(x.z - __bfloat162float(h23.x),
                                               x.w - __bfloat162float(h23.y));
    hi[2*i] = h01; hi[2*i+1] = h23;
    lo[2*i] = l01; lo[2*i+1] = l23;
}

// ---------------- dec_fea ----------------
__global__ void dec_fea_kernel(const float* __restrict__ s_t_hat,
                               const float* __restrict__ dec_W,
                               const float* __restrict__ dec_b) {
    const int warp = threadIdx.x >> 5, lane = threadIdx.x & 31;
    const int m = blockIdx.x * 8 + warp;
    const float* wr = dec_W + (size_t)m * NDIM + lane;
    float w[32];
#pragma unroll
    for (int j = 0; j < 32; ++j) w[j] = wr[j * 32];
    const float bias = dec_b[m];
    for (int b = 0; b < BB; ++b) {
        const float* s = s_t_hat + (size_t)b * NDIM + lane;
        float acc = 0.f;
#pragma unroll
        for (int j = 0; j < 32; ++j) acc += w[j] * s[j * 32];
#pragma unroll
        for (int off = 16; off; off >>= 1) acc += __shfl_down_sync(0xffffffffu, acc, off);
        if (lane == 0) g_dec_fea[b * NDIM + m] = acc + bias;
    }
}

// ---------------- score kernel: 128x256 CTA tile, bf16 hi/lo 3-pass ----------------
// 512 threads, warp grid 4x4, warp tile 32x64 (2x8 m16n8k16 frags).
// Kc=32, 3-stage cp.async pipeline, fused tanh·v epilogue.
#define PITCH  80
#define BUFA   (128*PITCH)                 /* 10240 */
#define BUFB   (256*PITCH)                 /* 20480 */
#define OFF_BH (2*BUFA)
#define OFF_BL (2*BUFA+BUFB)
#define STGB   (2*BUFA+2*BUFB)             /* 61440 */
#define OFF_DEC (3*STGB)                   /* 184320: 256 floats */
#define OFF_WC  (OFF_DEC+1024)
#define OFF_V   (OFF_WC+1024)
#define OFF_COV (OFF_V+1024)               /* 128 floats */
#define OFF_RED (OFF_COV+512)              /* 128*4 floats */
#define OFF_SC  (OFF_RED+2048)
#define SMEM_SZ (OFF_SC+512)               /* 190464 B */

__device__ __forceinline__ void load_stage(uint32_t sb, int s,
                                           int row0, int m0, int k0, int tid) {
    const uint32_t base = sb + s * STGB;
    {   // A: 128 rows x 4 chunks of 16B (hi+lo)
        const int row = tid >> 2, ch = tid & 3;
        const uint32_t o = row * PITCH + ch * 16;
        const size_t g = (size_t)(row0 + row) * NDIM + k0 + ch * 8;
        cp16(base + o,        g_h_hi + g);
        cp16(base + BUFA + o, g_h_lo + g);
    }
#pragma unroll
    for (int it = 0; it < 2; ++it) {   // B: 256 rows x 4 chunks (hi+lo)
        const int idx = tid + it * 512;
        const int row = idx >> 2, ch = idx & 3;
        const uint32_t o = row * PITCH + ch * 16;
        const size_t g = (size_t)(m0 + row) * NDIM + k0 + ch * 8;
        cp16(base + OFF_BH + o, g_w_hi + g);
        cp16(base + OFF_BL + o, g_w_lo + g);
    }
}

__global__ __launch_bounds__(512, 1)
void score_mma_kernel(const float* __restrict__ coverage,
                      const float* __restrict__ W_c,
                      const float* __restrict__ v) {
    extern __shared__ char smem[];
    const uint32_t sb = smem_to_u32(smem);
    const int tid  = threadIdx.x;
    const int lane = tid & 31;
    const int wid  = tid >> 5;
    const int wm   = wid >> 2;          // 0..3 (32-row slab)
    const int wn   = wid & 3;           // 0..3 (64-col slab)
    const int row0 = blockIdx.x * 128;
    const int b    = row0 / TT;

    float* dec_s = (float*)(smem + OFF_DEC);
    float* wc_s  = (float*)(smem + OFF_WC);
    float* v_s   = (float*)(smem + OFF_V);
    float* cov_s = (float*)(smem + OFF_COV);
    float* red   = (float*)(smem + OFF_RED);   // [128][4]
    float* sc_s  = (float*)(smem + OFF_SC);

    if (tid < 128) {
        cov_s[tid] = coverage[row0 + tid];
        sc_s[tid]  = 0.f;
    }

    // A (ldmatrix.x4): row = wm*32 + (l&7) + ((l>>3)&1)*8, byte (l>>4)*16
    const uint32_t aoff = (uint32_t)((wm*32 + (lane&7) + ((lane>>3)&1)*8) * PITCH + (lane>>4)*16);
    // B (ldmatrix.x2, lanes 0-15): row = wn*64 + (l&7), byte ((l>>3)&1)*16
    const uint32_t boff = (uint32_t)((wn*64 + (lane&7)) * PITCH + ((lane>>3)&1)*16);

    for (int nc = 0; nc < 4; ++nc) {
        const int m0 = nc * 256;
        if (tid < 256) {
            dec_s[tid] = g_dec_fea[b * NDIM + m0 + tid];
            wc_s[tid]  = W_c[m0 + tid];
            v_s[tid]   = v[m0 + tid];
        }

        float acc[2][8][4];
#pragma unroll
        for (int mi = 0; mi < 2; ++mi)
#pragma unroll
            for (int ni = 0; ni < 8; ++ni)
#pragma unroll
                for (int q = 0; q < 4; ++q) acc[mi][ni][q] = 0.f;

        load_stage(sb, 0, row0, m0, 0, tid);  CP_COMMIT();
        load_stage(sb, 1, row0, m0, 32, tid); CP_COMMIT();

        for (int ks = 0; ks < 32; ++ks) {
            const int s = ks % 3;
            if (ks + 2 < 32) CP_WAIT_1(); else CP_WAIT_0();
            __syncthreads();
            if (ks + 2 < 32) {
                load_stage(sb, (ks + 2) % 3, row0, m0, (ks + 2) * 32, tid);
                CP_COMMIT();
            }
            const uint32_t stg = sb + s * STGB;
#pragma unroll
            for (int kk = 0; kk < 2; ++kk) {
                uint32_t ah[2][4], al[2][4];
#pragma unroll
                for (int mi = 0; mi < 2; ++mi) {
                    const uint32_t a = stg + aoff + mi * (16 * PITCH) + kk * 32;
                    ldm_x4(ah[mi], a);
                    ldm_x4(al[mi], a + BUFA);
                }
                uint32_t bh[8][2], bl[8][2];
#pragma unroll
                for (int ni = 0; ni < 8; ++ni) {
                    const uint32_t bAddr = stg + OFF_BH + boff + ni * (8 * PITCH) + kk * 32;
                    ldm_x2(bh[ni], bAddr);
                    ldm_x2(bl[ni], bAddr + BUFB);
                }
#pragma unroll
                for (int mi = 0; mi < 2; ++mi)
#pragma unroll
                    for (int ni = 0; ni < 8; ++ni) {
                        mma16816(acc[mi][ni], ah[mi], bh[ni]);
                        mma16816(acc[mi][ni], al[mi], bh[ni]);
                        mma16816(acc[mi][ni], ah[mi], bl[ni]);
                    }
            }
        }

        // fused epilogue: tanh + dot with v over this 256-col chunk
        float part[2][2];
#pragma unroll
        for (int mi = 0; mi < 2; ++mi) { part[mi][0] = 0.f; part[mi][1] = 0.f; }
#pragma unroll
        for (int mi = 0; mi < 2; ++mi) {
            const int r0 = wm*32 + mi*16 + (lane >> 2);
            const float cv0 = cov_s[r0], cv1 = cov_s[r0 + 8];
#pragma unroll
            for (int ni = 0; ni < 8; ++ni) {
                const int c0 = wn*64 + ni*8 + (lane & 3)*2;
                const float d0 = dec_s[c0],  d1 = dec_s[c0+1];
                const float w0 = wc_s[c0],   w1 = wc_s[c0+1];
                const float q0 = v_s[c0],    q1 = v_s[c0+1];
                part[mi][0] += tanhf(acc[mi][ni][0] + d0 + cv0*w0) * q0
                             + tanhf(acc[mi][ni][1] + d1 + cv0*w1) * q1;
                part[mi][1] += tanhf(acc[mi][ni][2] + d0 + cv1*w0) * q0
                             + tanhf(acc[mi][ni][3] + d1 + cv1*w1) * q1;
            }
        }
#pragma unroll
        for (int mi = 0; mi < 2; ++mi)
#pragma unroll
            for (int i = 0; i < 2; ++i) {
                float p = part[mi][i];
                p += __shfl_xor_sync(0xffffffffu, p, 1);
                p += __shfl_xor_sync(0xffffffffu, p, 2);
                if ((lane & 3) == 0)
                    red[(wm*32 + mi*16 + (lane >> 2) + 8*i) * 4 + wn] = p;
            }
        __syncthreads();
        if (tid < 128)
            sc_s[tid] += red[tid*4] + red[tid*4+1] + red[tid*4+2] + red[tid*4+3];
        __syncthreads();
    }

    if (tid < 128) g_scores[row0 + tid] = sc_s[tid];
}

// ---------------- softmax ----------------
__global__ void softmax_kernel(const float* __restrict__ mask,
                               const float* __restrict__ coverage,
                               float* __restrict__ attn_out,
                               float* __restrict__ cov_out) {
    const int b = blockIdx.x, tid = threadIdx.x;
    __shared__ float wr_[8], stat[2];
    const float* sc = g_scores + b * TT;
    float sv[4], lmax = -1e30f;
#pragma unroll
    for (int q = 0; q < 4; ++q) { sv[q] = sc[tid + 256 * q]; lmax = fmaxf(lmax, sv[q]); }
#pragma unroll
    for (int off = 16; off; off >>= 1) lmax = fmaxf(lmax, __shfl_xor_sync(0xffffffffu, lmax, off));
    if ((tid & 31) == 0) wr_[tid >> 5] = lmax;
    __syncthreads();
    if (tid == 0) {
        float m = wr_[0];
#pragma unroll
        for (int i = 1; i < 8; ++i) m = fmaxf(m, wr_[i]);
        stat[0] = m;
    }
    __syncthreads();
    const float M = stat[0];
    float e[4], lsum = 0.f;
#pragma unroll
    for (int q = 0; q < 4; ++q) { e[q] = expf(sv[q] - M) * mask[b * TT + tid + 256 * q]; lsum += e[q]; }
#pragma unroll
    for (int off = 16; off; off >>= 1) lsum += __shfl_xor_sync(0xffffffffu, lsum, off);
    if ((tid & 31) == 0) wr_[tid >> 5] = lsum;
    __syncthreads();
    if (tid == 0) {
        float s = 0.f;
#pragma unroll
        for (int i = 0; i < 8; ++i) s += wr_[i];
        stat[1] = 1.0f / s;
    }
    __syncthreads();
    const float inv = stat[1];
#pragma unroll
    for (int q = 0; q < 4; ++q) {
        const int t = tid + 256 * q;
        const float a = e[q] * inv;
        attn_out[b * TT + t] = a;
        cov_out[b * TT + t]  = coverage[b * TT + t] + a;
    }
}

// ---------------- c_t: 4-way T-split + reduce ----------------
__global__ void ct_part_kernel(const float* __restrict__ h,
                               const float* __restrict__ attn) {
    const int b = blockIdx.x, nb = blockIdx.y, tc = blockIdx.z;
    const int n = nb * 128 + threadIdx.x;
    __shared__ float a_s[256];
    for (int i = threadIdx.x; i < 256; i += 128)
        a_s[i] = attn[b * TT + tc * 256 + i];
    __syncthreads();
    const float* hb = h + ((size_t)(b * TT + tc * 256)) * NDIM + n;
    float a0 = 0.f, a1 = 0.f, a2 = 0.f, a3 = 0.f;
#pragma unroll 4
    for (int t = 0; t < 256; t += 4) {
        a0 += a_s[t + 0] * hb[(size_t)(t + 0) * NDIM];
        a1 += a_s[t + 1] * hb[(size_t)(t + 1) * NDIM];
        a2 += a_s[t + 2] * hb[(size_t)(t + 2) * NDIM];
        a3 += a_s[t + 3] * hb[(size_t)(t + 3) * NDIM];
    }
    g_ct_part[((size_t)tc * BB + b) * NDIM + n] = (a0 + a1) + (a2 + a3);
}
__global__ void ct_reduce_kernel(float* __restrict__ c_t) {
    const int i = blockIdx.x * 256 + threadIdx.x;
    c_t[i] = (g_ct_part[i] + g_ct_part[i + BB * NDIM]) +
             (g_ct_part[i + 2 * BB * NDIM] + g_ct_part[i + 3 * BB * NDIM]);
}

// ---------------------------------------------------------------------------
extern "C" void kernel_launch(void* const* d_in, const int* in_sizes, int n_in,
                              void* d_out, int out_size) {
    const float* s_t_hat  = (const float*)d_in[0];
    const float* h        = (const float*)d_in[1];
    const float* mask     = (const float*)d_in[2];
    const float* coverage = (const float*)d_in[3];
    const float* W_h      = (const float*)d_in[4];
    const float* W_c      = (const float*)d_in[5];
    const float* dec_W    = (const float*)d_in[6];
    const float* dec_b    = (const float*)d_in[7];
    const float* v        = (const float*)d_in[8];

    float* out  = (float*)d_out;
    float* c_t  = out;
    float* attn = out + (size_t)BB * NDIM;
    float* covn = attn + (size_t)BB * TT;

    cudaFuncSetAttribute(score_mma_kernel,
                         cudaFuncAttributeMaxDynamicSharedMemorySize, SMEM_SZ);

    split_kernel<<<(int)((size_t)MTOT * NDIM / 4 / 256), 256>>>(h, 0);
    split_kernel<<<NDIM * NDIM / 4 / 256, 256>>>(W_h, 1);
    dec_fea_kernel<<<NDIM / 8, 256>>>(s_t_hat, dec_W, dec_b);
    score_mma_kernel<<<MTOT / 128, 512, SMEM_SZ>>>(coverage, W_c, v);
    softmax_kernel<<<BB, 256>>>(mask, coverage, attn, covn);
    ct_part_kernel<<<dim3(BB, NDIM / 128, 4), 128>>>(h, attn);
    ct_reduce_kernel<<<BB * NDIM / 256, 256>>>(c_t);
}

// round 7
// speedup vs baseline: 2.5578x; 1.0241x over previous
#include <cuda_runtime.h>
#include <cuda_bf16.h>
#include <math.h>
#include <stdint.h>

#define BB 64
#define TT 1024
#define NDIM 1024
#define MTOT (BB*TT)

__device__ __align__(16) __nv_bfloat16 g_h_hi[(size_t)MTOT*NDIM];
__device__ __align__(16) __nv_bfloat16 g_h_lo[(size_t)MTOT*NDIM];
__device__ __align__(16) __nv_bfloat16 g_w_hi[(size_t)NDIM*NDIM];
__device__ __align__(16) __nv_bfloat16 g_w_lo[(size_t)NDIM*NDIM];
__device__ float g_dec_fea[BB*NDIM];
__device__ float g_scores[MTOT];
__device__ float g_ct_part[4*BB*NDIM];

// ---------------- helpers ----------------
__device__ __forceinline__ uint32_t smem_to_u32(const void* p) {
    uint32_t a;
    asm("{ .reg .u64 t; cvta.to.shared.u64 t, %1; cvt.u32.u64 %0, t; }" : "=r"(a) : "l"(p));
    return a;
}
__device__ __forceinline__ void cp16(uint32_t dst, const void* src) {
    asm volatile("cp.async.cg.shared.global [%0], [%1], 16;" :: "r"(dst), "l"(src));
}
#define CP_COMMIT() asm volatile("cp.async.commit_group;" ::: "memory")
#define CP_WAIT_1() asm volatile("cp.async.wait_group 1;" ::: "memory")
#define CP_WAIT_0() asm volatile("cp.async.wait_group 0;" ::: "memory")

__device__ __forceinline__ void ldm_x4(uint32_t* r, uint32_t addr) {
    asm volatile("ldmatrix.sync.aligned.m8n8.x4.shared.b16 {%0,%1,%2,%3}, [%4];"
        : "=r"(r[0]), "=r"(r[1]), "=r"(r[2]), "=r"(r[3]) : "r"(addr));
}
__device__ __forceinline__ void mma16816(float* d, const uint32_t* a, const uint32_t* b) {
    asm volatile("mma.sync.aligned.m16n8k16.row.col.f32.bf16.bf16.f32 "
        "{%0,%1,%2,%3}, {%4,%5,%6,%7}, {%8,%9}, {%0,%1,%2,%3};"
        : "+f"(d[0]), "+f"(d[1]), "+f"(d[2]), "+f"(d[3])
        : "r"(a[0]), "r"(a[1]), "r"(a[2]), "r"(a[3]), "r"(b[0]), "r"(b[1]));
}

// ---------------- split f32 -> bf16 hi/lo ----------------
__global__ void split_kernel(const float* __restrict__ src, int is_w) {
    __nv_bfloat162* hi = (__nv_bfloat162*)(is_w ? g_w_hi : g_h_hi);
    __nv_bfloat162* lo = (__nv_bfloat162*)(is_w ? g_w_lo : g_h_lo);
    const size_t i = (size_t)blockIdx.x * 256 + threadIdx.x;
    float4 x = ((const float4*)src)[i];
    __nv_bfloat162 h01 = __floats2bfloat162_rn(x.x, x.y);
    __nv_bfloat162 h23 = __floats2bfloat162_rn(x.z, x.w);
    __nv_bfloat162 l01 = __floats2bfloat162_rn(x.x - __bfloat162float(h01.x),
                                               x.y - __bfloat162float(h01.y));
    __nv_bfloat162 l23 = __floats2bfloat162_rn(x.z - __bfloat162float(h23.x),
                                               x.w - __bfloat162float(h23.y));
    hi[2*i] = h01; hi[2*i+1] = h23;
    lo[2*i] = l01; lo[2*i+1] = l23;
}

// ---------------- dec_fea ----------------
__global__ void dec_fea_kernel(const float* __restrict__ s_t_hat,
                               const float* __restrict__ dec_W,
                               const float* __restrict__ dec_b) {
    const int warp = threadIdx.x >> 5, lane = threadIdx.x & 31;
    const int m = blockIdx.x * 8 + warp;
    const float* wr = dec_W + (size_t)m * NDIM + lane;
    float w[32];
#pragma unroll
    for (int j = 0; j < 32; ++j) w[j] = wr[j * 32];
    const float bias = dec_b[m];
    for (int b = 0; b < BB; ++b) {
        const float* s = s_t_hat + (size_t)b * NDIM + lane;
        float acc = 0.f;
#pragma unroll
        for (int j = 0; j < 32; ++j) acc += w[j] * s[j * 32];
#pragma unroll
        for (int off = 16; off; off >>= 1) acc += __shfl_down_sync(0xffffffffu, acc, off);
        if (lane == 0) g_dec_fea[b * NDIM + m] = acc + bias;
    }
}

// ---------------- score kernel: 128x256 CTA tile, 256 thr, warp tile 64x64 ----------------
#define PITCH  80
#define BUFA   (128*PITCH)                 /* 10240 */
#define BUFB   (256*PITCH)                 /* 20480 */
#define OFF_BH (2*BUFA)
#define OFF_BL (2*BUFA+BUFB)
#define STGB   (2*BUFA+2*BUFB)             /* 61440 */
#define OFF_DEC (3*STGB)                   /* 184320: 256 floats */
#define OFF_WC  (OFF_DEC+1024)
#define OFF_V   (OFF_WC+1024)
#define OFF_COV (OFF_V+1024)               /* 128 floats */
#define OFF_RED (OFF_COV+512)              /* 128*4 floats */
#define OFF_SC  (OFF_RED+2048)
#define SMEM_SZ (OFF_SC+512)               /* 190464 B */

__device__ __forceinline__ void load_stage(uint32_t sb, int s,
                                           int row0, int m0, int k0, int tid) {
    const uint32_t base = sb + s * STGB;
#pragma unroll
    for (int it = 0; it < 2; ++it) {   // A: 128 rows x 4 chunks (hi+lo)
        const int idx = tid + it * 256;
        const int row = idx >> 2, ch = idx & 3;
        const uint32_t o = row * PITCH + ch * 16;
        const size_t g = (size_t)(row0 + row) * NDIM + k0 + ch * 8;
        cp16(base + o,        g_h_hi + g);
        cp16(base + BUFA + o, g_h_lo + g);
    }
#pragma unroll
    for (int it = 0; it < 4; ++it) {   // B: 256 rows x 4 chunks (hi+lo)
        const int idx = tid + it * 256;
        const int row = idx >> 2, ch = idx & 3;
        const uint32_t o = row * PITCH + ch * 16;
        const size_t g = (size_t)(m0 + row) * NDIM + k0 + ch * 8;
        cp16(base + OFF_BH + o, g_w_hi + g);
        cp16(base + OFF_BL + o, g_w_lo + g);
    }
}

__global__ __launch_bounds__(256, 1)
void score_mma_kernel(const float* __restrict__ coverage,
                      const float* __restrict__ W_c,
                      const float* __restrict__ v) {
    extern __shared__ char smem[];
    const uint32_t sb = smem_to_u32(smem);
    const int tid  = threadIdx.x;
    const int lane = tid & 31;
    const int wid  = tid >> 5;
    const int wm   = wid >> 2;          // 0..1 (64-row slab)
    const int wn   = wid & 3;           // 0..3 (64-col slab)
    const int row0 = blockIdx.x * 128;
    const int b    = row0 / TT;

    float* dec_s = (float*)(smem + OFF_DEC);
    float* wc_s  = (float*)(smem + OFF_WC);
    float* v_s   = (float*)(smem + OFF_V);
    float* cov_s = (float*)(smem + OFF_COV);
    float* red   = (float*)(smem + OFF_RED);   // [128][4]
    float* sc_s  = (float*)(smem + OFF_SC);

    if (tid < 128) {
        cov_s[tid] = coverage[row0 + tid];
        sc_s[tid]  = 0.f;
    }

    // A (ldmatrix.x4, per kk): row = wm*64 + mi*16 + (l&7) + ((l>>3)&1)*8, byte (l>>4)*16 + kk*32
    const uint32_t aoff = (uint32_t)((wm*64 + (lane&7) + ((lane>>3)&1)*8) * PITCH + (lane>>4)*16);
    // B (ldmatrix.x4, both kk): row = wn*64 + ni*8 + (l&7), byte (l>>3)*16
    const uint32_t boff = (uint32_t)((wn*64 + (lane&7)) * PITCH + (lane>>3)*16);

    for (int nc = 0; nc < 4; ++nc) {
        const int m0 = nc * 256;
        if (tid < 256) {
            dec_s[tid] = g_dec_fea[b * NDIM + m0 + tid];
            wc_s[tid]  = W_c[m0 + tid];
            v_s[tid]   = v[m0 + tid];
        }

        float acc[4][8][4];
#pragma unroll
        for (int mi = 0; mi < 4; ++mi)
#pragma unroll
            for (int ni = 0; ni < 8; ++ni)
#pragma unroll
                for (int q = 0; q < 4; ++q) acc[mi][ni][q] = 0.f;

        load_stage(sb, 0, row0, m0, 0, tid);  CP_COMMIT();
        load_stage(sb, 1, row0, m0, 32, tid); CP_COMMIT();

        for (int ks = 0; ks < 32; ++ks) {
            const int s = ks % 3;
            if (ks + 2 < 32) CP_WAIT_1(); else CP_WAIT_0();
            __syncthreads();
            if (ks + 2 < 32) {
                load_stage(sb, (ks + 2) % 3, row0, m0, (ks + 2) * 32, tid);
                CP_COMMIT();
            }
            const uint32_t stg = sb + s * STGB;

            // B fragments for both kk halves: 8 ni x (hi,lo) x4
            uint32_t bh[8][4], bl[8][4];
#pragma unroll
            for (int ni = 0; ni < 8; ++ni) {
                const uint32_t bAddr = stg + OFF_BH + boff + ni * (8 * PITCH);
                ldm_x4(bh[ni], bAddr);
                ldm_x4(bl[ni], bAddr + BUFB);
            }
#pragma unroll
            for (int kk = 0; kk < 2; ++kk) {
                uint32_t ah[4][4], al[4][4];
#pragma unroll
                for (int mi = 0; mi < 4; ++mi) {
                    const uint32_t a = stg + aoff + mi * (16 * PITCH) + kk * 32;
                    ldm_x4(ah[mi], a);
                    ldm_x4(al[mi], a + BUFA);
                }
#pragma unroll
                for (int mi = 0; mi < 4; ++mi)
#pragma unroll
                    for (int ni = 0; ni < 8; ++ni) {
                        mma16816(acc[mi][ni], ah[mi], &bh[ni][kk*2]);
                        mma16816(acc[mi][ni], al[mi], &bh[ni][kk*2]);
                        mma16816(acc[mi][ni], ah[mi], &bl[ni][kk*2]);
                    }
            }
        }

        // fused epilogue: tanh + dot with v over this 256-col chunk
        float part[4][2];
#pragma unroll
        for (int mi = 0; mi < 4; ++mi) { part[mi][0] = 0.f; part[mi][1] = 0.f; }
#pragma unroll
        for (int mi = 0; mi < 4; ++mi) {
            const int r0 = wm*64 + mi*16 + (lane >> 2);
            const float cv0 = cov_s[r0], cv1 = cov_s[r0 + 8];
#pragma unroll
            for (int ni = 0; ni < 8; ++ni) {
                const int c0 = wn*64 + ni*8 + (lane & 3)*2;
                const float d0 = dec_s[c0],  d1 = dec_s[c0+1];
                const float w0 = wc_s[c0],   w1 = wc_s[c0+1];
                const float q0 = v_s[c0],    q1 = v_s[c0+1];
                part[mi][0] += tanhf(acc[mi][ni][0] + d0 + cv0*w0) * q0
                             + tanhf(acc[mi][ni][1] + d1 + cv0*w1) * q1;
                part[mi][1] += tanhf(acc[mi][ni][2] + d0 + cv1*w0) * q0
                             + tanhf(acc[mi][ni][3] + d1 + cv1*w1) * q1;
            }
        }
#pragma unroll
        for (int mi = 0; mi < 4; ++mi)
#pragma unroll
            for (int i = 0; i < 2; ++i) {
                float p = part[mi][i];
                p += __shfl_xor_sync(0xffffffffu, p, 1);
                p += __shfl_xor_sync(0xffffffffu, p, 2);
                if ((lane & 3) == 0)
                    red[(wm*64 + mi*16 + (lane >> 2) + 8*i) * 4 + wn] = p;
            }
        __syncthreads();
        if (tid < 128)
            sc_s[tid] += red[tid*4] + red[tid*4+1] + red[tid*4+2] + red[tid*4+3];
        __syncthreads();
    }

    if (tid < 128) g_scores[row0 + tid] = sc_s[tid];
}

// ---------------- softmax ----------------
__global__ void softmax_kernel(const float* __restrict__ mask,
                               const float* __restrict__ coverage,
                               float* __restrict__ attn_out,
                               float* __restrict__ cov_out) {
    const int b = blockIdx.x, tid = threadIdx.x;
    __shared__ float wr_[8], stat[2];
    const float* sc = g_scores + b * TT;
    float sv[4], lmax = -1e30f;
#pragma unroll
    for (int q = 0; q < 4; ++q) { sv[q] = sc[tid + 256 * q]; lmax = fmaxf(lmax, sv[q]); }
#pragma unroll
    for (int off = 16; off; off >>= 1) lmax = fmaxf(lmax, __shfl_xor_sync(0xffffffffu, lmax, off));
    if ((tid & 31) == 0) wr_[tid >> 5] = lmax;
    __syncthreads();
    if (tid == 0) {
        float m = wr_[0];
#pragma unroll
        for (int i = 1; i < 8; ++i) m = fmaxf(m, wr_[i]);
        stat[0] = m;
    }
    __syncthreads();
    const float M = stat[0];
    float e[4], lsum = 0.f;
#pragma unroll
    for (int q = 0; q < 4; ++q) { e[q] = expf(sv[q] - M) * mask[b * TT + tid + 256 * q]; lsum += e[q]; }
#pragma unroll
    for (int off = 16; off; off >>= 1) lsum += __shfl_xor_sync(0xffffffffu, lsum, off);
    if ((tid & 31) == 0) wr_[tid >> 5] = lsum;
    __syncthreads();
    if (tid == 0) {
        float s = 0.f;
#pragma unroll
        for (int i = 0; i < 8; ++i) s += wr_[i];
        stat[1] = 1.0f / s;
    }
    __syncthreads();
    const float inv = stat[1];
#pragma unroll
    for (int q = 0; q < 4; ++q) {
        const int t = tid + 256 * q;
        const float a = e[q] * inv;
        attn_out[b * TT + t] = a;
        cov_out[b * TT + t]  = coverage[b * TT + t] + a;
    }
}

// ---------------- c_t: 4-way T-split + reduce ----------------
__global__ void ct_part_kernel(const float* __restrict__ h,
                               const float* __restrict__ attn) {
    const int b = blockIdx.x, nb = blockIdx.y, tc = blockIdx.z;
    const int n = nb * 128 + threadIdx.x;
    __shared__ float a_s[256];
    for (int i = threadIdx.x; i < 256; i += 128)
        a_s[i] = attn[b * TT + tc * 256 + i];
    __syncthreads();
    const float* hb = h + ((size_t)(b * TT + tc * 256)) * NDIM + n;
    float a0 = 0.f, a1 = 0.f, a2 = 0.f, a3 = 0.f;
#pragma unroll 4
    for (int t = 0; t < 256; t += 4) {
        a0 += a_s[t + 0] * hb[(size_t)(t + 0) * NDIM];
        a1 += a_s[t + 1] * hb[(size_t)(t + 1) * NDIM];
        a2 += a_s[t + 2] * hb[(size_t)(t + 2) * NDIM];
        a3 += a_s[t + 3] * hb[(size_t)(t + 3) * NDIM];
    }
    g_ct_part[((size_t)tc * BB + b) * NDIM + n] = (a0 + a1) + (a2 + a3);
}
__global__ void ct_reduce_kernel(float* __restrict__ c_t) {
    const int i = blockIdx.x * 256 + threadIdx.x;
    c_t[i] = (g_ct_part[i] + g_ct_part[i + BB * NDIM]) +
             (g_ct_part[i + 2 * BB * NDIM] + g_ct_part[i + 3 * BB * NDIM]);
}

// ---------------------------------------------------------------------------
extern "C" void kernel_launch(void* const* d_in, const int* in_sizes, int n_in,
                              void* d_out, int out_size) {
    const float* s_t_hat  = (const float*)d_in[0];
    const float* h        = (const float*)d_in[1];
    const float* mask     = (const float*)d_in[2];
    const float* coverage = (const float*)d_in[3];
    const float* W_h      = (const float*)d_in[4];
    const float* W_c      = (const float*)d_in[5];
    const float* dec_W    = (const float*)d_in[6];
    const float* dec_b    = (const float*)d_in[7];
    const float* v        = (const float*)d_in[8];

    float* out  = (float*)d_out;
    float* c_t  = out;
    float* attn = out + (size_t)BB * NDIM;
    float* covn = attn + (size_t)BB * TT;

    cudaFuncSetAttribute(score_mma_kernel,
                         cudaFuncAttributeMaxDynamicSharedMemorySize, SMEM_SZ);

    split_kernel<<<(int)((size_t)MTOT * NDIM / 4 / 256), 256>>>(h, 0);
    split_kernel<<<NDIM * NDIM / 4 / 256, 256>>>(W_h, 1);
    dec_fea_kernel<<<NDIM / 8, 256>>>(s_t_hat, dec_W, dec_b);
    score_mma_kernel<<<MTOT / 128, 256, SMEM_SZ>>>(coverage, W_c, v);
    softmax_kernel<<<BB, 256>>>(mask, coverage, attn, covn);
    ct_part_kernel<<<dim3(BB, NDIM / 128, 4), 128>>>(h, attn);
    ct_reduce_kernel<<<BB * NDIM / 256, 256>>>(c_t);
}

// round 8
// speedup vs baseline: 3.4060x; 1.3316x over previous
#include <cuda_runtime.h>
#include <cuda_fp16.h>
#include <math.h>
#include <stdint.h>

#define BB 64
#define TT 1024
#define NDIM 1024
#define MTOT (BB*TT)

__device__ __align__(16) __half g_h_hi[(size_t)MTOT*NDIM];
__device__ __align__(16) __half g_h_lo[(size_t)MTOT*NDIM];
__device__ __align__(16) __half g_w[(size_t)NDIM*NDIM];
__device__ float g_dec_fea[BB*NDIM];
__device__ float g_scores[MTOT];
__device__ float g_ct_part[4*BB*NDIM];

// ---------------- helpers ----------------
__device__ __forceinline__ uint32_t smem_to_u32(const void* p) {
    uint32_t a;
    asm("{ .reg .u64 t; cvta.to.shared.u64 t, %1; cvt.u32.u64 %0, t; }" : "=r"(a) : "l"(p));
    return a;
}
__device__ __forceinline__ void cp16(uint32_t dst, const void* src) {
    asm volatile("cp.async.cg.shared.global [%0], [%1], 16;" :: "r"(dst), "l"(src));
}
#define CP_COMMIT() asm volatile("cp.async.commit_group;" ::: "memory")
#define CP_WAIT_2() asm volatile("cp.async.wait_group 2;" ::: "memory")
#define CP_WAIT_0() asm volatile("cp.async.wait_group 0;" ::: "memory")

__device__ __forceinline__ void ldm_x4(uint32_t* r, uint32_t addr) {
    asm volatile("ldmatrix.sync.aligned.m8n8.x4.shared.b16 {%0,%1,%2,%3}, [%4];"
        : "=r"(r[0]), "=r"(r[1]), "=r"(r[2]), "=r"(r[3]) : "r"(addr));
}
__device__ __forceinline__ void mma16816(float* d, const uint32_t* a, const uint32_t* b) {
    asm volatile("mma.sync.aligned.m16n8k16.row.col.f32.f16.f16.f32 "
        "{%0,%1,%2,%3}, {%4,%5,%6,%7}, {%8,%9}, {%0,%1,%2,%3};"
        : "+f"(d[0]), "+f"(d[1]), "+f"(d[2]), "+f"(d[3])
        : "r"(a[0]), "r"(a[1]), "r"(a[2]), "r"(a[3]), "r"(b[0]), "r"(b[1]));
}

// ---------------- split h -> fp16 hi/lo ----------------
__global__ void split_h_kernel(const float* __restrict__ src) {
    const size_t i = (size_t)blockIdx.x * 256 + threadIdx.x;
    float4 x = ((const float4*)src)[i];
    __half h0 = __float2half_rn(x.x), h1 = __float2half_rn(x.y);
    __half h2 = __float2half_rn(x.z), h3 = __float2half_rn(x.w);
    __half l0 = __float2half_rn(x.x - __half2float(h0));
    __half l1 = __float2half_rn(x.y - __half2float(h1));
    __half l2 = __float2half_rn(x.z - __half2float(h2));
    __half l3 = __float2half_rn(x.w - __half2float(h3));
    __half2* H = (__half2*)g_h_hi;
    __half2* L = (__half2*)g_h_lo;
    H[2*i]   = __halves2half2(h0, h1);
    H[2*i+1] = __halves2half2(h2, h3);
    L[2*i]   = __halves2half2(l0, l1);
    L[2*i+1] = __halves2half2(l2, l3);
}
// ---------------- convert W -> fp16 ----------------
__global__ void conv_w_kernel(const float* __restrict__ src) {
    const size_t i = (size_t)blockIdx.x * 256 + threadIdx.x;
    float4 x = ((const float4*)src)[i];
    __half2* W = (__half2*)g_w;
    W[2*i]   = __halves2half2(__float2half_rn(x.x), __float2half_rn(x.y));
    W[2*i+1] = __halves2half2(__float2half_rn(x.z), __float2half_rn(x.w));
}

// ---------------- dec_fea ----------------
__global__ void dec_fea_kernel(const float* __restrict__ s_t_hat,
                               const float* __restrict__ dec_W,
                               const float* __restrict__ dec_b) {
    const int warp = threadIdx.x >> 5, lane = threadIdx.x & 31;
    const int m = blockIdx.x * 8 + warp;
    const float* wr = dec_W + (size_t)m * NDIM + lane;
    float w[32];
#pragma unroll
    for (int j = 0; j < 32; ++j) w[j] = wr[j * 32];
    const float bias = dec_b[m];
    for (int b = 0; b < BB; ++b) {
        const float* s = s_t_hat + (size_t)b * NDIM + lane;
        float acc = 0.f;
#pragma unroll
        for (int j = 0; j < 32; ++j) acc += w[j] * s[j * 32];
#pragma unroll
        for (int off = 16; off; off >>= 1) acc += __shfl_down_sync(0xffffffffu, acc, off);
        if (lane == 0) g_dec_fea[b * NDIM + m] = acc + bias;
    }
}

// ---------------- score kernel: fp16 2-pass, 128x256 tile, 4-stage pipeline ----------------
#define PITCH  80
#define BUFA   (128*PITCH)                 /* 10240 */
#define BUFB   (256*PITCH)                 /* 20480 */
#define OFF_B  (2*BUFA)
#define STGB   (2*BUFA+BUFB)               /* 40960 */
#define NSTG   4
#define OFF_DEC (NSTG*STGB)                /* 163840: 256 floats */
#define OFF_WC  (OFF_DEC+1024)
#define OFF_V   (OFF_WC+1024)
#define OFF_COV (OFF_V+1024)               /* 128 floats */
#define OFF_RED (OFF_COV+512)              /* 128*4 floats */
#define OFF_SC  (OFF_RED+2048)
#define SMEM_SZ (OFF_SC+512)               /* 169984 B */

__device__ __forceinline__ void load_stage(uint32_t sb, int s,
                                           int row0, int m0, int k0, int tid) {
    const uint32_t base = sb + s * STGB;
#pragma unroll
    for (int it = 0; it < 2; ++it) {   // A: 128 rows x 4 chunks (hi+lo)
        const int idx = tid + it * 256;
        const int row = idx >> 2, ch = idx & 3;
        const uint32_t o = row * PITCH + ch * 16;
        const size_t g = (size_t)(row0 + row) * NDIM + k0 + ch * 8;
        cp16(base + o,        g_h_hi + g);
        cp16(base + BUFA + o, g_h_lo + g);
    }
#pragma unroll
    for (int it = 0; it < 4; ++it) {   // B: 256 rows x 4 chunks
        const int idx = tid + it * 256;
        const int row = idx >> 2, ch = idx & 3;
        const uint32_t o = row * PITCH + ch * 16;
        const size_t g = (size_t)(m0 + row) * NDIM + k0 + ch * 8;
        cp16(base + OFF_B + o, g_w + g);
    }
}

__global__ __launch_bounds__(256, 1)
void score_mma_kernel(const float* __restrict__ coverage,
                      const float* __restrict__ W_c,
                      const float* __restrict__ v) {
    extern __shared__ char smem[];
    const uint32_t sb = smem_to_u32(smem);
    const int tid  = threadIdx.x;
    const int lane = tid & 31;
    const int wid  = tid >> 5;
    const int wm   = wid >> 2;          // 0..1 (64-row slab)
    const int wn   = wid & 3;           // 0..3 (64-col slab)
    const int row0 = blockIdx.x * 128;
    const int b    = row0 / TT;

    float* dec_s = (float*)(smem + OFF_DEC);
    float* wc_s  = (float*)(smem + OFF_WC);
    float* v_s   = (float*)(smem + OFF_V);
    float* cov_s = (float*)(smem + OFF_COV);
    float* red   = (float*)(smem + OFF_RED);   // [128][4]
    float* sc_s  = (float*)(smem + OFF_SC);

    if (tid < 128) {
        cov_s[tid] = coverage[row0 + tid];
        sc_s[tid]  = 0.f;
    }

    const uint32_t aoff = (uint32_t)((wm*64 + (lane&7) + ((lane>>3)&1)*8) * PITCH + (lane>>4)*16);
    const uint32_t boff = (uint32_t)((wn*64 + (lane&7)) * PITCH + (lane>>3)*16);

    for (int nc = 0; nc < 4; ++nc) {
        const int m0 = nc * 256;
        dec_s[tid] = g_dec_fea[b * NDIM + m0 + tid];
        wc_s[tid]  = W_c[m0 + tid];
        v_s[tid]   = v[m0 + tid];

        float acc[4][8][4];
#pragma unroll
        for (int mi = 0; mi < 4; ++mi)
#pragma unroll
            for (int ni = 0; ni < 8; ++ni)
#pragma unroll
                for (int q = 0; q < 4; ++q) acc[mi][ni][q] = 0.f;

        load_stage(sb, 0, row0, m0, 0,  tid); CP_COMMIT();
        load_stage(sb, 1, row0, m0, 32, tid); CP_COMMIT();
        load_stage(sb, 2, row0, m0, 64, tid); CP_COMMIT();

        for (int ks = 0; ks < 32; ++ks) {
            const int s = ks & 3;
            if (ks + 3 < 32) CP_WAIT_2(); else CP_WAIT_0();
            __syncthreads();
            if (ks + 3 < 32) {
                load_stage(sb, (ks + 3) & 3, row0, m0, (ks + 3) * 32, tid);
                CP_COMMIT();
            }
            const uint32_t stg = sb + s * STGB;

            // B fragments (both kk halves): 8 ni x4
            uint32_t bh[8][4];
#pragma unroll
            for (int ni = 0; ni < 8; ++ni)
                ldm_x4(bh[ni], stg + OFF_B + boff + ni * (8 * PITCH));
#pragma unroll
            for (int kk = 0; kk < 2; ++kk) {
                uint32_t ah[4][4], al[4][4];
#pragma unroll
                for (int mi = 0; mi < 4; ++mi) {
                    const uint32_t a = stg + aoff + mi * (16 * PITCH) + kk * 32;
                    ldm_x4(ah[mi], a);
                    ldm_x4(al[mi], a + BUFA);
                }
#pragma unroll
                for (int mi = 0; mi < 4; ++mi)
#pragma unroll
                    for (int ni = 0; ni < 8; ++ni) {
                        mma16816(acc[mi][ni], ah[mi], &bh[ni][kk*2]);
                        mma16816(acc[mi][ni], al[mi], &bh[ni][kk*2]);
                    }
            }
        }

        // fused epilogue: tanh + dot with v over this 256-col chunk
        float part[4][2];
#pragma unroll
        for (int mi = 0; mi < 4; ++mi) { part[mi][0] = 0.f; part[mi][1] = 0.f; }
#pragma unroll
        for (int mi = 0; mi < 4; ++mi) {
            const int r0 = wm*64 + mi*16 + (lane >> 2);
            const float cv0 = cov_s[r0], cv1 = cov_s[r0 + 8];
#pragma unroll
            for (int ni = 0; ni < 8; ++ni) {
                const int c0 = wn*64 + ni*8 + (lane & 3)*2;
                const float d0 = dec_s[c0],  d1 = dec_s[c0+1];
                const float w0 = wc_s[c0],   w1 = wc_s[c0+1];
                const float q0 = v_s[c0],    q1 = v_s[c0+1];
                part[mi][0] += tanhf(acc[mi][ni][0] + d0 + cv0*w0) * q0
                             + tanhf(acc[mi][ni][1] + d1 + cv0*w1) * q1;
                part[mi][1] += tanhf(acc[mi][ni][2] + d0 + cv1*w0) * q0
                             + tanhf(acc[mi][ni][3] + d1 + cv1*w1) * q1;
            }
        }
#pragma unroll
        for (int mi = 0; mi < 4; ++mi)
#pragma unroll
            for (int i = 0; i < 2; ++i) {
                float p = part[mi][i];
                p += __shfl_xor_sync(0xffffffffu, p, 1);
                p += __shfl_xor_sync(0xffffffffu, p, 2);
                if ((lane & 3) == 0)
                    red[(wm*64 + mi*16 + (lane >> 2) + 8*i) * 4 + wn] = p;
            }
        __syncthreads();
        if (tid < 128)
            sc_s[tid] += red[tid*4] + red[tid*4+1] + red[tid*4+2] + red[tid*4+3];
        __syncthreads();
    }

    if (tid < 128) g_scores[row0 + tid] = sc_s[tid];
}

// ---------------- softmax ----------------
__global__ void softmax_kernel(const float* __restrict__ mask,
                               const float* __restrict__ coverage,
                               float* __restrict__ attn_out,
                               float* __restrict__ cov_out) {
    const int b = blockIdx.x, tid = threadIdx.x;
    __shared__ float wr_[8], stat[2];
    const float* sc = g_scores + b * TT;
    float sv[4], lmax = -1e30f;
#pragma unroll
    for (int q = 0; q < 4; ++q) { sv[q] = sc[tid + 256 * q]; lmax = fmaxf(lmax, sv[q]); }
#pragma unroll
    for (int off = 16; off; off >>= 1) lmax = fmaxf(lmax, __shfl_xor_sync(0xffffffffu, lmax, off));
    if ((tid & 31) == 0) wr_[tid >> 5] = lmax;
    __syncthreads();
    if (tid == 0) {
        float m = wr_[0];
#pragma unroll
        for (int i = 1; i < 8; ++i) m = fmaxf(m, wr_[i]);
        stat[0] = m;
    }
    __syncthreads();
    const float M = stat[0];
    float e[4], lsum = 0.f;
#pragma unroll
    for (int q = 0; q < 4; ++q) { e[q] = expf(sv[q] - M) * mask[b * TT + tid + 256 * q]; lsum += e[q]; }
#pragma unroll
    for (int off = 16; off; off >>= 1) lsum += __shfl_xor_sync(0xffffffffu, lsum, off);
    if ((tid & 31) == 0) wr_[tid >> 5] = lsum;
    __syncthreads();
    if (tid == 0) {
        float s = 0.f;
#pragma unroll
        for (int i = 0; i < 8; ++i) s += wr_[i];
        stat[1] = 1.0f / s;
    }
    __syncthreads();
    const float inv = stat[1];
#pragma unroll
    for (int q = 0; q < 4; ++q) {
        const int t = tid + 256 * q;
        const float a = e[q] * inv;
        attn_out[b * TT + t] = a;
        cov_out[b * TT + t]  = coverage[b * TT + t] + a;
    }
}

// ---------------- c_t: 4-way T-split + reduce ----------------
__global__ void ct_part_kernel(const float* __restrict__ h,
                               const float* __restrict__ attn) {
    const int b = blockIdx.x, nb = blockIdx.y, tc = blockIdx.z;
    const int n = nb * 128 + threadIdx.x;
    __shared__ float a_s[256];
    for (int i = threadIdx.x; i < 256; i += 128)
        a_s[i] = attn[b * TT + tc * 256 + i];
    __syncthreads();
    const float* hb = h + ((size_t)(b * TT + tc * 256)) * NDIM + n;
    float a0 = 0.f, a1 = 0.f, a2 = 0.f, a3 = 0.f;
#pragma unroll 4
    for (int t = 0; t < 256; t += 4) {
        a0 += a_s[t + 0] * hb[(size_t)(t + 0) * NDIM];
        a1 += a_s[t + 1] * hb[(size_t)(t + 1) * NDIM];
        a2 += a_s[t + 2] * hb[(size_t)(t + 2) * NDIM];
        a3 += a_s[t + 3] * hb[(size_t)(t + 3) * NDIM];
    }
    g_ct_part[((size_t)tc * BB + b) * NDIM + n] = (a0 + a1) + (a2 + a3);
}
__global__ void ct_reduce_kernel(float* __restrict__ c_t) {
    const int i = blockIdx.x * 256 + threadIdx.x;
    c_t[i] = (g_ct_part[i] + g_ct_part[i + BB * NDIM]) +
             (g_ct_part[i + 2 * BB * NDIM] + g_ct_part[i + 3 * BB * NDIM]);
}

// ---------------------------------------------------------------------------
extern "C" void kernel_launch(void* const* d_in, const int* in_sizes, int n_in,
                              void* d_out, int out_size) {
    const float* s_t_hat  = (const float*)d_in[0];
    const float* h        = (const float*)d_in[1];
    const float* mask     = (const float*)d_in[2];
    const float* coverage = (const float*)d_in[3];
    const float* W_h      = (const float*)d_in[4];
    const float* W_c      = (const float*)d_in[5];
    const float* dec_W    = (const float*)d_in[6];
    const float* dec_b    = (const float*)d_in[7];
    const float* v        = (const float*)d_in[8];

    float* out  = (float*)d_out;
    float* c_t  = out;
    float* attn = out + (size_t)BB * NDIM;
    float* covn = attn + (size_t)BB * TT;

    cudaFuncSetAttribute(score_mma_kernel,
                         cudaFuncAttributeMaxDynamicSharedMemorySize, SMEM_SZ);

    split_h_kernel<<<(int)((size_t)MTOT * NDIM / 4 / 256), 256>>>(h);
    conv_w_kernel<<<NDIM * NDIM / 4 / 256, 256>>>(W_h);
    dec_fea_kernel<<<NDIM / 8, 256>>>(s_t_hat, dec_W, dec_b);
    score_mma_kernel<<<MTOT / 128, 256, SMEM_SZ>>>(coverage, W_c, v);
    softmax_kernel<<<BB, 256>>>(mask, coverage, attn, covn);
    ct_part_kernel<<<dim3(BB, NDIM / 128, 4), 128>>>(h, attn);
    ct_reduce_kernel<<<BB * NDIM / 256, 256>>>(c_t);
}

// round 9
// speedup vs baseline: 4.7065x; 1.3818x over previous
#include <cuda_runtime.h>
#include <cuda_fp16.h>
#include <math.h>
#include <stdint.h>

#define BB 64
#define TT 1024
#define NDIM 1024
#define MTOT (BB*TT)

__device__ __align__(16) __half g_h16[(size_t)MTOT*NDIM];
__device__ __align__(16) __half g_w[(size_t)NDIM*NDIM];
__device__ float g_dec_fea[BB*NDIM];
__device__ float g_scores[MTOT];
__device__ float g_ct_part[4*BB*NDIM];

// ---------------- helpers ----------------
__device__ __forceinline__ uint32_t smem_to_u32(const void* p) {
    uint32_t a;
    asm("{ .reg .u64 t; cvta.to.shared.u64 t, %1; cvt.u32.u64 %0, t; }" : "=r"(a) : "l"(p));
    return a;
}
__device__ __forceinline__ void cp16(uint32_t dst, const void* src) {
    asm volatile("cp.async.cg.shared.global [%0], [%1], 16;" :: "r"(dst), "l"(src));
}
#define CP_COMMIT() asm volatile("cp.async.commit_group;" ::: "memory")
#define CP_WAIT_2() asm volatile("cp.async.wait_group 2;" ::: "memory")
#define CP_WAIT_0() asm volatile("cp.async.wait_group 0;" ::: "memory")

__device__ __forceinline__ void ldm_x4(uint32_t* r, uint32_t addr) {
    asm volatile("ldmatrix.sync.aligned.m8n8.x4.shared.b16 {%0,%1,%2,%3}, [%4];"
        : "=r"(r[0]), "=r"(r[1]), "=r"(r[2]), "=r"(r[3]) : "r"(addr));
}
__device__ __forceinline__ void mma16816(float* d, const uint32_t* a, const uint32_t* b) {
    asm volatile("mma.sync.aligned.m16n8k16.row.col.f32.f16.f16.f32 "
        "{%0,%1,%2,%3}, {%4,%5,%6,%7}, {%8,%9}, {%0,%1,%2,%3};"
        : "+f"(d[0]), "+f"(d[1]), "+f"(d[2]), "+f"(d[3])
        : "r"(a[0]), "r"(a[1]), "r"(a[2]), "r"(a[3]), "r"(b[0]), "r"(b[1]));
}

// ---------------- convert f32 -> fp16 ----------------
__global__ void conv_h_kernel(const float* __restrict__ src) {
    const size_t i = (size_t)blockIdx.x * 256 + threadIdx.x;
    float4 x = ((const float4*)src)[i];
    __half2* H = (__half2*)g_h16;
    H[2*i]   = __halves2half2(__float2half_rn(x.x), __float2half_rn(x.y));
    H[2*i+1] = __halves2half2(__float2half_rn(x.z), __float2half_rn(x.w));
}
__global__ void conv_w_kernel(const float* __restrict__ src) {
    const size_t i = (size_t)blockIdx.x * 256 + threadIdx.x;
    float4 x = ((const float4*)src)[i];
    __half2* W = (__half2*)g_w;
    W[2*i]   = __halves2half2(__float2half_rn(x.x), __float2half_rn(x.y));
    W[2*i+1] = __halves2half2(__float2half_rn(x.z), __float2half_rn(x.w));
}

// ---------------- dec_fea ----------------
__global__ void dec_fea_kernel(const float* __restrict__ s_t_hat,
                               const float* __restrict__ dec_W,
                               const float* __restrict__ dec_b) {
    const int warp = threadIdx.x >> 5, lane = threadIdx.x & 31;
    const int m = blockIdx.x * 8 + warp;
    const float* wr = dec_W + (size_t)m * NDIM + lane;
    float w[32];
#pragma unroll
    for (int j = 0; j < 32; ++j) w[j] = wr[j * 32];
    const float bias = dec_b[m];
    for (int b = 0; b < BB; ++b) {
        const float* s = s_t_hat + (size_t)b * NDIM + lane;
        float acc = 0.f;
#pragma unroll
        for (int j = 0; j < 32; ++j) acc += w[j] * s[j * 32];
#pragma unroll
        for (int off = 16; off; off >>= 1) acc += __shfl_down_sync(0xffffffffu, acc, off);
        if (lane == 0) g_dec_fea[b * NDIM + m] = acc + bias;
    }
}

// ---------------- score kernel: fp16 single-pass, 128x256 tile, 4-stage ----------------
#define PITCH  80
#define BUFA   (128*PITCH)                 /* 10240 */
#define BUFB   (256*PITCH)                 /* 20480 */
#define OFF_B  BUFA
#define STGB   (BUFA+BUFB)                 /* 30720 */
#define NSTG   4
#define OFF_DEC (NSTG*STGB)                /* 122880: 256 floats */
#define OFF_WC  (OFF_DEC+1024)
#define OFF_V   (OFF_WC+1024)
#define OFF_COV (OFF_V+1024)               /* 128 floats */
#define OFF_RED (OFF_COV+512)              /* 128*4 floats */
#define OFF_SC  (OFF_RED+2048)
#define SMEM_SZ (OFF_SC+512)               /* 129024 B */

__device__ __forceinline__ void load_stage(uint32_t sb, int s,
                                           int row0, int m0, int k0, int tid) {
    const uint32_t base = sb + s * STGB;
#pragma unroll
    for (int it = 0; it < 2; ++it) {   // A: 128 rows x 4 chunks
        const int idx = tid + it * 256;
        const int row = idx >> 2, ch = idx & 3;
        const uint32_t o = row * PITCH + ch * 16;
        const size_t g = (size_t)(row0 + row) * NDIM + k0 + ch * 8;
        cp16(base + o, g_h16 + g);
    }
#pragma unroll
    for (int it = 0; it < 4; ++it) {   // B: 256 rows x 4 chunks
        const int idx = tid + it * 256;
        const int row = idx >> 2, ch = idx & 3;
        const uint32_t o = row * PITCH + ch * 16;
        const size_t g = (size_t)(m0 + row) * NDIM + k0 + ch * 8;
        cp16(base + OFF_B + o, g_w + g);
    }
}

__global__ __launch_bounds__(256, 1)
void score_mma_kernel(const float* __restrict__ coverage,
                      const float* __restrict__ W_c,
                      const float* __restrict__ v) {
    extern __shared__ char smem[];
    const uint32_t sb = smem_to_u32(smem);
    const int tid  = threadIdx.x;
    const int lane = tid & 31;
    const int wid  = tid >> 5;
    const int wm   = wid >> 2;          // 0..1 (64-row slab)
    const int wn   = wid & 3;           // 0..3 (64-col slab)
    const int row0 = blockIdx.x * 128;
    const int b    = row0 / TT;

    float* dec_s = (float*)(smem + OFF_DEC);
    float* wc_s  = (float*)(smem + OFF_WC);
    float* v_s   = (float*)(smem + OFF_V);
    float* cov_s = (float*)(smem + OFF_COV);
    float* red   = (float*)(smem + OFF_RED);   // [128][4]
    float* sc_s  = (float*)(smem + OFF_SC);

    if (tid < 128) {
        cov_s[tid] = coverage[row0 + tid];
        sc_s[tid]  = 0.f;
    }

    const uint32_t aoff = (uint32_t)((wm*64 + (lane&7) + ((lane>>3)&1)*8) * PITCH + (lane>>4)*16);
    const uint32_t boff = (uint32_t)((wn*64 + (lane&7)) * PITCH + (lane>>3)*16);

    for (int nc = 0; nc < 4; ++nc) {
        const int m0 = nc * 256;
        dec_s[tid] = g_dec_fea[b * NDIM + m0 + tid];
        wc_s[tid]  = W_c[m0 + tid];
        v_s[tid]   = v[m0 + tid];

        float acc[4][8][4];
#pragma unroll
        for (int mi = 0; mi < 4; ++mi)
#pragma unroll
            for (int ni = 0; ni < 8; ++ni)
#pragma unroll
                for (int q = 0; q < 4; ++q) acc[mi][ni][q] = 0.f;

        load_stage(sb, 0, row0, m0, 0,  tid); CP_COMMIT();
        load_stage(sb, 1, row0, m0, 32, tid); CP_COMMIT();
        load_stage(sb, 2, row0, m0, 64, tid); CP_COMMIT();

        for (int ks = 0; ks < 32; ++ks) {
            const int s = ks & 3;
            if (ks + 3 < 32) CP_WAIT_2(); else CP_WAIT_0();
            __syncthreads();
            if (ks + 3 < 32) {
                load_stage(sb, (ks + 3) & 3, row0, m0, (ks + 3) * 32, tid);
                CP_COMMIT();
            }
            const uint32_t stg = sb + s * STGB;

            uint32_t bh[8][4];
#pragma unroll
            for (int ni = 0; ni < 8; ++ni)
                ldm_x4(bh[ni], stg + OFF_B + boff + ni * (8 * PITCH));
#pragma unroll
            for (int kk = 0; kk < 2; ++kk) {
                uint32_t ah[4][4];
#pragma unroll
                for (int mi = 0; mi < 4; ++mi)
                    ldm_x4(ah[mi], stg + aoff + mi * (16 * PITCH) + kk * 32);
#pragma unroll
                for (int mi = 0; mi < 4; ++mi)
#pragma unroll
                    for (int ni = 0; ni < 8; ++ni)
                        mma16816(acc[mi][ni], ah[mi], &bh[ni][kk*2]);
            }
        }

        // fused epilogue: tanh + dot with v over this 256-col chunk
        float part[4][2];
#pragma unroll
        for (int mi = 0; mi < 4; ++mi) { part[mi][0] = 0.f; part[mi][1] = 0.f; }
#pragma unroll
        for (int mi = 0; mi < 4; ++mi) {
            const int r0 = wm*64 + mi*16 + (lane >> 2);
            const float cv0 = cov_s[r0], cv1 = cov_s[r0 + 8];
#pragma unroll
            for (int ni = 0; ni < 8; ++ni) {
                const int c0 = wn*64 + ni*8 + (lane & 3)*2;
                const float d0 = dec_s[c0],  d1 = dec_s[c0+1];
                const float w0 = wc_s[c0],   w1 = wc_s[c0+1];
                const float q0 = v_s[c0],    q1 = v_s[c0+1];
                part[mi][0] += tanhf(acc[mi][ni][0] + d0 + cv0*w0) * q0
                             + tanhf(acc[mi][ni][1] + d1 + cv0*w1) * q1;
                part[mi][1] += tanhf(acc[mi][ni][2] + d0 + cv1*w0) * q0
                             + tanhf(acc[mi][ni][3] + d1 + cv1*w1) * q1;
            }
        }
#pragma unroll
        for (int mi = 0; mi < 4; ++mi)
#pragma unroll
            for (int i = 0; i < 2; ++i) {
                float p = part[mi][i];
                p += __shfl_xor_sync(0xffffffffu, p, 1);
                p += __shfl_xor_sync(0xffffffffu, p, 2);
                if ((lane & 3) == 0)
                    red[(wm*64 + mi*16 + (lane >> 2) + 8*i) * 4 + wn] = p;
            }
        __syncthreads();
        if (tid < 128)
            sc_s[tid] += red[tid*4] + red[tid*4+1] + red[tid*4+2] + red[tid*4+3];
        __syncthreads();
    }

    if (tid < 128) g_scores[row0 + tid] = sc_s[tid];
}

// ---------------- softmax ----------------
__global__ void softmax_kernel(const float* __restrict__ mask,
                               const float* __restrict__ coverage,
                               float* __restrict__ attn_out,
                               float* __restrict__ cov_out) {
    const int b = blockIdx.x, tid = threadIdx.x;
    __shared__ float wr_[8], stat[2];
    const float* sc = g_scores + b * TT;
    float sv[4], lmax = -1e30f;
#pragma unroll
    for (int q = 0; q < 4; ++q) { sv[q] = sc[tid + 256 * q]; lmax = fmaxf(lmax, sv[q]); }
#pragma unroll
    for (int off = 16; off; off >>= 1) lmax = fmaxf(lmax, __shfl_xor_sync(0xffffffffu, lmax, off));
    if ((tid & 31) == 0) wr_[tid >> 5] = lmax;
    __syncthreads();
    if (tid == 0) {
        float m = wr_[0];
#pragma unroll
        for (int i = 1; i < 8; ++i) m = fmaxf(m, wr_[i]);
        stat[0] = m;
    }
    __syncthreads();
    const float M = stat[0];
    float e[4], lsum = 0.f;
#pragma unroll
    for (int q = 0; q < 4; ++q) { e[q] = expf(sv[q] - M) * mask[b * TT + tid + 256 * q]; lsum += e[q]; }
#pragma unroll
    for (int off = 16; off; off >>= 1) lsum += __shfl_xor_sync(0xffffffffu, lsum, off);
    if ((tid & 31) == 0) wr_[tid >> 5] = lsum;
    __syncthreads();
    if (tid == 0) {
        float s = 0.f;
#pragma unroll
        for (int i = 0; i < 8; ++i) s += wr_[i];
        stat[1] = 1.0f / s;
    }
    __syncthreads();
    const float inv = stat[1];
#pragma unroll
    for (int q = 0; q < 4; ++q) {
        const int t = tid + 256 * q;
        const float a = e[q] * inv;
        attn_out[b * TT + t] = a;
        cov_out[b * TT + t]  = coverage[b * TT + t] + a;
    }
}

// ---------------- c_t: 4-way T-split + reduce ----------------
__global__ void ct_part_kernel(const float* __restrict__ h,
                               const float* __restrict__ attn) {
    const int b = blockIdx.x, nb = blockIdx.y, tc = blockIdx.z;
    const int n = nb * 128 + threadIdx.x;
    __shared__ float a_s[256];
    for (int i = threadIdx.x; i < 256; i += 128)
        a_s[i] = attn[b * TT + tc * 256 + i];
    __syncthreads();
    const float* hb = h + ((size_t)(b * TT + tc * 256)) * NDIM + n;
    float a0 = 0.f, a1 = 0.f, a2 = 0.f, a3 = 0.f;
#pragma unroll 4
    for (int t = 0; t < 256; t += 4) {
        a0 += a_s[t + 0] * hb[(size_t)(t + 0) * NDIM];
        a1 += a_s[t + 1] * hb[(size_t)(t + 1) * NDIM];
        a2 += a_s[t + 2] * hb[(size_t)(t + 2) * NDIM];
        a3 += a_s[t + 3] * hb[(size_t)(t + 3) * NDIM];
    }
    g_ct_part[((size_t)tc * BB + b) * NDIM + n] = (a0 + a1) + (a2 + a3);
}
__global__ void ct_reduce_kernel(float* __restrict__ c_t) {
    const int i = blockIdx.x * 256 + threadIdx.x;
    c_t[i] = (g_ct_part[i] + g_ct_part[i + BB * NDIM]) +
             (g_ct_part[i + 2 * BB * NDIM] + g_ct_part[i + 3 * BB * NDIM]);
}

// ---------------------------------------------------------------------------
extern "C" void kernel_launch(void* const* d_in, const int* in_sizes, int n_in,
                              void* d_out, int out_size) {
    const float* s_t_hat  = (const float*)d_in[0];
    const float* h        = (const float*)d_in[1];
    const float* mask     = (const float*)d_in[2];
    const float* coverage = (const float*)d_in[3];
    const float* W_h      = (const float*)d_in[4];
    const float* W_c      = (const float*)d_in[5];
    const float* dec_W    = (const float*)d_in[6];
    const float* dec_b    = (const float*)d_in[7];
    const float* v        = (const float*)d_in[8];

    float* out  = (float*)d_out;
    float* c_t  = out;
    float* attn = out + (size_t)BB * NDIM;
    float* covn = attn + (size_t)BB * TT;

    cudaFuncSetAttribute(score_mma_kernel,
                         cudaFuncAttributeMaxDynamicSharedMemorySize, SMEM_SZ);

    conv_h_kernel<<<(int)((size_t)MTOT * NDIM / 4 / 256), 256>>>(h);
    conv_w_kernel<<<NDIM * NDIM / 4 / 256, 256>>>(W_h);
    dec_fea_kernel<<<NDIM / 8, 256>>>(s_t_hat, dec_W, dec_b);
    score_mma_kernel<<<MTOT / 128, 256, SMEM_SZ>>>(coverage, W_c, v);
    softmax_kernel<<<BB, 256>>>(mask, coverage, attn, covn);
    ct_part_kernel<<<dim3(BB, NDIM / 128, 4), 128>>>(h, attn);
    ct_reduce_kernel<<<BB * NDIM / 256, 256>>>(c_t);
}

// round 10
// speedup vs baseline: 5.3802x; 1.1431x over previous
#include <cuda_runtime.h>
#include <cuda_fp16.h>
#include <math.h>
#include <stdint.h>

#define BB 64
#define TT 1024
#define NDIM 1024
#define MTOT (BB*TT)

__device__ __align__(16) __half g_h16[(size_t)MTOT*NDIM];
__device__ __align__(16) __half g_w[(size_t)NDIM*NDIM];
__device__ float g_dec_fea[BB*NDIM];
__device__ float g_scores[MTOT];
__device__ float g_ct_part[4*BB*NDIM];

// ---------------- helpers ----------------
__device__ __forceinline__ uint32_t smem_to_u32(const void* p) {
    uint32_t a;
    asm("{ .reg .u64 t; cvta.to.shared.u64 t, %1; cvt.u32.u64 %0, t; }" : "=r"(a) : "l"(p));
    return a;
}
__device__ __forceinline__ void cp16(uint32_t dst, const void* src) {
    asm volatile("cp.async.cg.shared.global [%0], [%1], 16;" :: "r"(dst), "l"(src));
}
#define CP_COMMIT() asm volatile("cp.async.commit_group;" ::: "memory")
#define CP_WAIT_2() asm volatile("cp.async.wait_group 2;" ::: "memory")
#define CP_WAIT_0() asm volatile("cp.async.wait_group 0;" ::: "memory")

__device__ __forceinline__ void ldm_x4(uint32_t* r, uint32_t addr) {
    asm volatile("ldmatrix.sync.aligned.m8n8.x4.shared.b16 {%0,%1,%2,%3}, [%4];"
        : "=r"(r[0]), "=r"(r[1]), "=r"(r[2]), "=r"(r[3]) : "r"(addr));
}
__device__ __forceinline__ void mma16816(float* d, const uint32_t* a, const uint32_t* b) {
    asm volatile("mma.sync.aligned.m16n8k16.row.col.f32.f16.f16.f32 "
        "{%0,%1,%2,%3}, {%4,%5,%6,%7}, {%8,%9}, {%0,%1,%2,%3};"
        : "+f"(d[0]), "+f"(d[1]), "+f"(d[2]), "+f"(d[3])
        : "r"(a[0]), "r"(a[1]), "r"(a[2]), "r"(a[3]), "r"(b[0]), "r"(b[1]));
}

// ---------------- convert f32 -> fp16 ----------------
__global__ void conv_h_kernel(const float* __restrict__ src) {
    const size_t i = (size_t)blockIdx.x * 256 + threadIdx.x;
    float4 x = ((const float4*)src)[i];
    __half2* H = (__half2*)g_h16;
    H[2*i]   = __halves2half2(__float2half_rn(x.x), __float2half_rn(x.y));
    H[2*i+1] = __halves2half2(__float2half_rn(x.z), __float2half_rn(x.w));
}
__global__ void conv_w_kernel(const float* __restrict__ src) {
    const size_t i = (size_t)blockIdx.x * 256 + threadIdx.x;
    float4 x = ((const float4*)src)[i];
    __half2* W = (__half2*)g_w;
    W[2*i]   = __halves2half2(__float2half_rn(x.x), __float2half_rn(x.y));
    W[2*i+1] = __halves2half2(__float2half_rn(x.z), __float2half_rn(x.w));
}

// ---------------- dec_fea ----------------
__global__ void dec_fea_kernel(const float* __restrict__ s_t_hat,
                               const float* __restrict__ dec_W,
                               const float* __restrict__ dec_b) {
    const int warp = threadIdx.x >> 5, lane = threadIdx.x & 31;
    const int m = blockIdx.x * 8 + warp;
    const float* wr = dec_W + (size_t)m * NDIM + lane;
    float w[32];
#pragma unroll
    for (int j = 0; j < 32; ++j) w[j] = wr[j * 32];
    const float bias = dec_b[m];
    for (int b = 0; b < BB; ++b) {
        const float* s = s_t_hat + (size_t)b * NDIM + lane;
        float acc = 0.f;
#pragma unroll
        for (int j = 0; j < 32; ++j) acc += w[j] * s[j * 32];
#pragma unroll
        for (int off = 16; off; off >>= 1) acc += __shfl_down_sync(0xffffffffu, acc, off);
        if (lane == 0) g_dec_fea[b * NDIM + m] = acc + bias;
    }
}

// ---------------- score kernel: 64x256 CTA tile, 128 thr, 2 CTAs/SM ----------------
#define PITCH  80
#define BUFA   (64*PITCH)                  /* 5120 */
#define BUFB   (256*PITCH)                 /* 20480 */
#define OFF_B  BUFA
#define STGB   (BUFA+BUFB)                 /* 25600 */
#define NSTG   4
#define OFF_DEC (NSTG*STGB)                /* 102400: 256 floats */
#define OFF_WC  (OFF_DEC+1024)
#define OFF_V   (OFF_WC+1024)
#define OFF_COV (OFF_V+1024)               /* 64 floats */
#define OFF_RED (OFF_COV+256)              /* 64*4 floats */
#define OFF_SC  (OFF_RED+1024)
#define SMEM_SZ (OFF_SC+256)               /* 107008 B */

__device__ __forceinline__ void load_stage(uint32_t sb, int s,
                                           int row0, int m0, int k0, int tid) {
    const uint32_t base = sb + s * STGB;
#pragma unroll
    for (int it = 0; it < 2; ++it) {   // A: 64 rows x 4 chunks
        const int idx = tid + it * 128;
        const int row = idx >> 2, ch = idx & 3;
        const uint32_t o = row * PITCH + ch * 16;
        const size_t g = (size_t)(row0 + row) * NDIM + k0 + ch * 8;
        cp16(base + o, g_h16 + g);
    }
#pragma unroll
    for (int it = 0; it < 8; ++it) {   // B: 256 rows x 4 chunks
        const int idx = tid + it * 128;
        const int row = idx >> 2, ch = idx & 3;
        const uint32_t o = row * PITCH + ch * 16;
        const size_t g = (size_t)(m0 + row) * NDIM + k0 + ch * 8;
        cp16(base + OFF_B + o, g_w + g);
    }
}

__global__ __launch_bounds__(128, 2)
void score_mma_kernel(const float* __restrict__ coverage,
                      const float* __restrict__ W_c,
                      const float* __restrict__ v) {
    extern __shared__ char smem[];
    const uint32_t sb = smem_to_u32(smem);
    const int tid  = threadIdx.x;
    const int lane = tid & 31;
    const int wn   = tid >> 5;          // warp = 64-col slab, all 64 rows
    const int row0 = blockIdx.x * 64;
    const int b    = row0 / TT;

    float* dec_s = (float*)(smem + OFF_DEC);
    float* wc_s  = (float*)(smem + OFF_WC);
    float* v_s   = (float*)(smem + OFF_V);
    float* cov_s = (float*)(smem + OFF_COV);
    float* red   = (float*)(smem + OFF_RED);   // [64][4]
    float* sc_s  = (float*)(smem + OFF_SC);

    if (tid < 64) {
        cov_s[tid] = coverage[row0 + tid];
        sc_s[tid]  = 0.f;
    }

    const uint32_t aoff = (uint32_t)(((lane&7) + ((lane>>3)&1)*8) * PITCH + (lane>>4)*16);
    const uint32_t boff = (uint32_t)((wn*64 + (lane&7)) * PITCH + (lane>>3)*16);

    for (int nc = 0; nc < 4; ++nc) {
        const int m0 = nc * 256;
        dec_s[tid]       = g_dec_fea[b * NDIM + m0 + tid];
        dec_s[tid + 128] = g_dec_fea[b * NDIM + m0 + tid + 128];
        wc_s[tid]        = W_c[m0 + tid];
        wc_s[tid + 128]  = W_c[m0 + tid + 128];
        v_s[tid]         = v[m0 + tid];
        v_s[tid + 128]   = v[m0 + tid + 128];

        float acc[4][8][4];
#pragma unroll
        for (int mi = 0; mi < 4; ++mi)
#pragma unroll
            for (int ni = 0; ni < 8; ++ni)
#pragma unroll
                for (int q = 0; q < 4; ++q) acc[mi][ni][q] = 0.f;

        load_stage(sb, 0, row0, m0, 0,  tid); CP_COMMIT();
        load_stage(sb, 1, row0, m0, 32, tid); CP_COMMIT();
        load_stage(sb, 2, row0, m0, 64, tid); CP_COMMIT();

        for (int ks = 0; ks < 32; ++ks) {
            const int s = ks & 3;
            if (ks + 3 < 32) CP_WAIT_2(); else CP_WAIT_0();
            __syncthreads();
            if (ks + 3 < 32) {
                load_stage(sb, (ks + 3) & 3, row0, m0, (ks + 3) * 32, tid);
                CP_COMMIT();
            }
            const uint32_t stg = sb + s * STGB;

            uint32_t bh[8][4];
#pragma unroll
            for (int ni = 0; ni < 8; ++ni)
                ldm_x4(bh[ni], stg + OFF_B + boff + ni * (8 * PITCH));
#pragma unroll
            for (int kk = 0; kk < 2; ++kk) {
                uint32_t ah[4][4];
#pragma unroll
                for (int mi = 0; mi < 4; ++mi)
                    ldm_x4(ah[mi], stg + aoff + mi * (16 * PITCH) + kk * 32);
#pragma unroll
                for (int mi = 0; mi < 4; ++mi)
#pragma unroll
                    for (int ni = 0; ni < 8; ++ni)
                        mma16816(acc[mi][ni], ah[mi], &bh[ni][kk*2]);
            }
        }

        // fused epilogue: tanh + dot with v over this 256-col chunk
        float part[4][2];
#pragma unroll
        for (int mi = 0; mi < 4; ++mi) { part[mi][0] = 0.f; part[mi][1] = 0.f; }
#pragma unroll
        for (int mi = 0; mi < 4; ++mi) {
            const int r0 = mi*16 + (lane >> 2);
            const float cv0 = cov_s[r0], cv1 = cov_s[r0 + 8];
#pragma unroll
            for (int ni = 0; ni < 8; ++ni) {
                const int c0 = wn*64 + ni*8 + (lane & 3)*2;
                const float d0 = dec_s[c0],  d1 = dec_s[c0+1];
                const float w0 = wc_s[c0],   w1 = wc_s[c0+1];
                const float q0 = v_s[c0],    q1 = v_s[c0+1];
                part[mi][0] += tanhf(acc[mi][ni][0] + d0 + cv0*w0) * q0
                             + tanhf(acc[mi][ni][1] + d1 + cv0*w1) * q1;
                part[mi][1] += tanhf(acc[mi][ni][2] + d0 + cv1*w0) * q0
                             + tanhf(acc[mi][ni][3] + d1 + cv1*w1) * q1;
            }
        }
#pragma unroll
        for (int mi = 0; mi < 4; ++mi)
#pragma unroll
            for (int i = 0; i < 2; ++i) {
                float p = part[mi][i];
                p += __shfl_xor_sync(0xffffffffu, p, 1);
                p += __shfl_xor_sync(0xffffffffu, p, 2);
                if ((lane & 3) == 0)
                    red[(mi*16 + (lane >> 2) + 8*i) * 4 + wn] = p;
            }
        __syncthreads();
        if (tid < 64)
            sc_s[tid] += red[tid*4] + red[tid*4+1] + red[tid*4+2] + red[tid*4+3];
        __syncthreads();
    }

    if (tid < 64) g_scores[row0 + tid] = sc_s[tid];
}

// ---------------- softmax ----------------
__global__ void softmax_kernel(const float* __restrict__ mask,
                               const float* __restrict__ coverage,
                               float* __restrict__ attn_out,
                               float* __restrict__ cov_out) {
    const int b = blockIdx.x, tid = threadIdx.x;
    __shared__ float wr_[8], stat[2];
    const float* sc = g_scores + b * TT;
    float sv[4], lmax = -1e30f;
#pragma unroll
    for (int q = 0; q < 4; ++q) { sv[q] = sc[tid + 256 * q]; lmax = fmaxf(lmax, sv[q]); }
#pragma unroll
    for (int off = 16; off; off >>= 1) lmax = fmaxf(lmax, __shfl_xor_sync(0xffffffffu, lmax, off));
    if ((tid & 31) == 0) wr_[tid >> 5] = lmax;
    __syncthreads();
    if (tid == 0) {
        float m = wr_[0];
#pragma unroll
        for (int i = 1; i < 8; ++i) m = fmaxf(m, wr_[i]);
        stat[0] = m;
    }
    __syncthreads();
    const float M = stat[0];
    float e[4], lsum = 0.f;
#pragma unroll
    for (int q = 0; q < 4; ++q) { e[q] = expf(sv[q] - M) * mask[b * TT + tid + 256 * q]; lsum += e[q]; }
#pragma unroll
    for (int off = 16; off; off >>= 1) lsum += __shfl_xor_sync(0xffffffffu, lsum, off);
    if ((tid & 31) == 0) wr_[tid >> 5] = lsum;
    __syncthreads();
    if (tid == 0) {
        float s = 0.f;
#pragma unroll
        for (int i = 0; i < 8; ++i) s += wr_[i];
        stat[1] = 1.0f / s;
    }
    __syncthreads();
    const float inv = stat[1];
#pragma unroll
    for (int q = 0; q < 4; ++q) {
        const int t = tid + 256 * q;
        const float a = e[q] * inv;
        attn_out[b * TT + t] = a;
        cov_out[b * TT + t]  = coverage[b * TT + t] + a;
    }
}

// ---------------- c_t: 4-way T-split + reduce ----------------
__global__ void ct_part_kernel(const float* __restrict__ h,
                               const float* __restrict__ attn) {
    const int b = blockIdx.x, nb = blockIdx.y, tc = blockIdx.z;
    const int n = nb * 128 + threadIdx.x;
    __shared__ float a_s[256];
    for (int i = threadIdx.x; i < 256; i += 128)
        a_s[i] = attn[b * TT + tc * 256 + i];
    __syncthreads();
    const float* hb = h + ((size_t)(b * TT + tc * 256)) * NDIM + n;
    float a0 = 0.f, a1 = 0.f, a2 = 0.f, a3 = 0.f;
#pragma unroll 4
    for (int t = 0; t < 256; t += 4) {
        a0 += a_s[t + 0] * hb[(size_t)(t + 0) * NDIM];
        a1 += a_s[t + 1] * hb[(size_t)(t + 1) * NDIM];
        a2 += a_s[t + 2] * hb[(size_t)(t + 2) * NDIM];
        a3 += a_s[t + 3] * hb[(size_t)(t + 3) * NDIM];
    }
    g_ct_part[((size_t)tc * BB + b) * NDIM + n] = (a0 + a1) + (a2 + a3);
}
__global__ void ct_reduce_kernel(float* __restrict__ c_t) {
    const int i = blockIdx.x * 256 + threadIdx.x;
    c_t[i] = (g_ct_part[i] + g_ct_part[i + BB * NDIM]) +
             (g_ct_part[i + 2 * BB * NDIM] + g_ct_part[i + 3 * BB * NDIM]);
}

// ---------------------------------------------------------------------------
extern "C" void kernel_launch(void* const* d_in, const int* in_sizes, int n_in,
                              void* d_out, int out_size) {
    const float* s_t_hat  = (const float*)d_in[0];
    const float* h        = (const float*)d_in[1];
    const float* mask     = (const float*)d_in[2];
    const float* coverage = (const float*)d_in[3];
    const float* W_h      = (const float*)d_in[4];
    const float* W_c      = (const float*)d_in[5];
    const float* dec_W    = (const float*)d_in[6];
    const float* dec_b    = (const float*)d_in[7];
    const float* v        = (const float*)d_in[8];

    float* out  = (float*)d_out;
    float* c_t  = out;
    float* attn = out + (size_t)BB * NDIM;
    float* covn = attn + (size_t)BB * TT;

    cudaFuncSetAttribute(score_mma_kernel,
                         cudaFuncAttributeMaxDynamicSharedMemorySize, SMEM_SZ);

    conv_h_kernel<<<(int)((size_t)MTOT * NDIM / 4 / 256), 256>>>(h);
    conv_w_kernel<<<NDIM * NDIM / 4 / 256, 256>>>(W_h);
    dec_fea_kernel<<<NDIM / 8, 256>>>(s_t_hat, dec_W, dec_b);
    score_mma_kernel<<<MTOT / 64, 128, SMEM_SZ>>>(coverage, W_c, v);
    softmax_kernel<<<BB, 256>>>(mask, coverage, attn, covn);
    ct_part_kernel<<<dim3(BB, NDIM / 128, 4), 128>>>(h, attn);
    ct_reduce_kernel<<<BB * NDIM / 256, 256>>>(c_t);
}